// round 7
// baseline (speedup 1.0000x reference)
#include <cuda_runtime.h>
#include <cstddef>

typedef unsigned long long ull;

#define NB 64
#define NT 256
#define NIN 1024
#define NH 2048
#define NM 512
#define NHM 2560
#define NG 1536
#define NBLK 128
#define NTHR 512

// proj (N=256) tile layout
#define SA_STRIDE 96
#define SB_STRIDE 288
#define SA_BUF 3072
#define SB_BUF 9216
// loop (N=128, dup-B) tile layout
#define SA_STR 96
#define SBD_STR 260
#define SA_SLAB 3072
#define SBD_SLAB 8320
#define DYN_BYTES 98304

// ---------------- device scratch ----------------
__device__ float g_xp[(size_t)NB * NT * NH];
__device__ float g_h[2 * NB * NM];
__device__ float g_linraw[NB * NH];
__device__ float g_pp[(size_t)8 * NB * NH];    // P partials (8 splits)
__device__ float g_ps1[NBLK];
__device__ float g_ps2[NBLK];
__device__ float g_gp[(size_t)10 * NB * NG];   // G partials (<=10 splits)
__device__ float g_cWc[(size_t)NH * NM];
__device__ float g_cbc[NH];
__device__ float g_dcoef[2 * NM];
__device__ unsigned g_flags[NBLK];             // zero-init
__device__ unsigned g_sense2;                  // zero-init

// ---------------- f32x2 helpers ----------------
__device__ __forceinline__ void fma2(ull &d, ull a, ull b) {
    asm("fma.rn.f32x2 %0, %1, %2, %0;" : "+l"(d) : "l"(a), "l"(b));
}
__device__ __forceinline__ ull dup2(float x) {
    ull r; asm("mov.b64 %0, {%1, %1};" : "=l"(r) : "f"(x)); return r;
}
__device__ __forceinline__ float2 unp(ull v) {
    float2 r; asm("mov.b64 {%0, %1}, %2;" : "=f"(r.x), "=f"(r.y) : "l"(v)); return r;
}

// ---------------- flag-based grid barrier (no atomics) ----------------
__device__ __forceinline__ void gbarf(unsigned &epoch) {
    __syncthreads();
    epoch++;
    if (blockIdx.x == 0) {
        int t = threadIdx.x;
        if (t >= 1 && t < NBLK) {
            unsigned v;
            do {
                asm volatile("ld.global.acquire.gpu.u32 %0, [%1];"
                             : "=r"(v) : "l"(g_flags + t) : "memory");
            } while ((int)(v - epoch) < 0);
        }
        __syncthreads();
        if (threadIdx.x == 0) {
            __threadfence();
            asm volatile("st.global.release.gpu.u32 [%0], %1;"
                         :: "l"(&g_sense2), "r"(epoch) : "memory");
        }
    } else {
        if (threadIdx.x == 0) {
            __threadfence();
            asm volatile("st.global.release.gpu.u32 [%0], %1;"
                         :: "l"(g_flags + blockIdx.x), "r"(epoch) : "memory");
            unsigned v;
            do {
                asm volatile("ld.global.acquire.gpu.u32 %0, [%1];"
                             : "=r"(v) : "l"(&g_sense2) : "memory");
            } while ((int)(v - epoch) < 0);
        }
    }
    __syncthreads();
}

// ---------------- proj inner: 64x256 tile, acc[4][4] ----------------
__device__ __forceinline__ void mm_k32(ull acc[4][4], const float* sAb, const float* sBb,
                                       int r0, int c0) {
#pragma unroll 8
    for (int k = 0; k < 32; k++) {
        int rot = k & 28;
        const float* ar = sAb + k * SA_STRIDE + rot + r0;
        ull a0 = *(const ull*)(ar);
        ull a1 = *(const ull*)(ar + 2);
        ull a2 = *(const ull*)(ar + 4);
        ull a3 = *(const ull*)(ar + 6);
        float4 bf = *(const float4*)(sBb + k * SB_STRIDE + rot + c0);
        ull b0 = dup2(bf.x), b1 = dup2(bf.y), b2 = dup2(bf.z), b3 = dup2(bf.w);
        fma2(acc[0][0], a0, b0); fma2(acc[0][1], a0, b1); fma2(acc[0][2], a0, b2); fma2(acc[0][3], a0, b3);
        fma2(acc[1][0], a1, b0); fma2(acc[1][1], a1, b1); fma2(acc[1][2], a1, b2); fma2(acc[1][3], a1, b3);
        fma2(acc[2][0], a2, b0); fma2(acc[2][1], a2, b1); fma2(acc[2][2], a2, b2); fma2(acc[2][3], a2, b3);
        fma2(acc[3][0], a3, b0); fma2(acc[3][1], a3, b1); fma2(acc[3][2], a3, b2); fma2(acc[3][3], a3, b3);
    }
}

// ---------------- loop inner: 64x128 tile, dup-B, acc[4][2] ----------------
__device__ __forceinline__ void mm128(ull acc[4][2], const float* sAb, const float* sBb,
                                      int r0, int c0d) {
#pragma unroll 8
    for (int k = 0; k < 32; k++) {
        int rot = k & 28;
        const float* ar = sAb + k * SA_STR + rot + r0;
        ull a0 = *(const ull*)(ar);
        ull a1 = *(const ull*)(ar + 2);
        ull a2 = *(const ull*)(ar + 4);
        ull a3 = *(const ull*)(ar + 6);
        ulonglong2 bb = *(const ulonglong2*)(sBb + k * SBD_STR + c0d);
        fma2(acc[0][0], a0, bb.x); fma2(acc[0][1], a0, bb.y);
        fma2(acc[1][0], a1, bb.x); fma2(acc[1][1], a1, bb.y);
        fma2(acc[2][0], a2, bb.x); fma2(acc[2][1], a2, bb.y);
        fma2(acc[3][0], a3, bb.x); fma2(acc[3][1], a3, bb.y);
    }
}

// proj stores (N=256, non-dup)
#define STORE_AB(bsel) do { \
    float* dA = sA + (bsel) * SA_BUF + (akq * 4) * SA_STRIDE + akq * 4 + arow; \
    dA[0] = ra.x; dA[SA_STRIDE] = ra.y; dA[2 * SA_STRIDE] = ra.z; dA[3 * SA_STRIDE] = ra.w; \
    _Pragma("unroll") \
    for (int i2 = 0; i2 < 4; i2++) { \
        float* dB = sB + (bsel) * SB_BUF + (bkq[i2] * 4) * SB_STRIDE + bkq[i2] * 4 + bcol[i2]; \
        dB[0] = rb4[i2].x; dB[SB_STRIDE] = rb4[i2].y; \
        dB[2 * SB_STRIDE] = rb4[i2].z; dB[3 * SB_STRIDE] = rb4[i2].w; \
    } \
} while (0)

// loop stores (N=128, dup-B)
#define STORE_A128(bsel) do { \
    float* dA = sA2 + (bsel) * SA_SLAB + (akq * 4) * SA_STR + akq * 4 + arow; \
    dA[0] = ra.x; dA[SA_STR] = ra.y; dA[2 * SA_STR] = ra.z; dA[3 * SA_STR] = ra.w; \
} while (0)

#define STORE_B128(bsel) do { \
    _Pragma("unroll") \
    for (int i2 = 0; i2 < 2; i2++) { \
        float* dB = sBD2 + (bsel) * SBD_SLAB + (gkq[i2] * 4) * SBD_STR + 2 * gcol[i2]; \
        *(float2*)(dB)                = make_float2(rb[i2].x, rb[i2].x); \
        *(float2*)(dB + SBD_STR)      = make_float2(rb[i2].y, rb[i2].y); \
        *(float2*)(dB + 2 * SBD_STR)  = make_float2(rb[i2].z, rb[i2].z); \
        *(float2*)(dB + 3 * SBD_STR)  = make_float2(rb[i2].w, rb[i2].w); \
    } \
} while (0)

__global__ void __launch_bounds__(NTHR)
ltc_all(const float* __restrict__ x,      const float* __restrict__ hidden,
        const float* __restrict__ W_in,   const float* __restrict__ b_in,
        const float* __restrict__ cell_W, const float* __restrict__ cell_b,
        const float* __restrict__ upd_W,  const float* __restrict__ upd_b,
        const float* __restrict__ rst_W,  const float* __restrict__ rst_b,
        const float* __restrict__ tau,
        const float* __restrict__ lc_W,   const float* __restrict__ lc_b,
        const float* __restrict__ sk_W,   const float* __restrict__ sk_b,
        const float* __restrict__ fb_W,   const float* __restrict__ fb_b,
        const float* __restrict__ ln_w,   const float* __restrict__ ln_b,
        const float* __restrict__ mn_w,   const float* __restrict__ mn_b,
        float* __restrict__ out)
{
    extern __shared__ float dyn[];
    float* sA   = dyn;                  // proj A (2 x 3072)
    float* sB   = dyn + 2 * SA_BUF;     // proj B (2 x 9216)
    float* sA2  = dyn;                  // loop A (2 x 3072)
    float* sBD2 = dyn + 2 * SA_SLAB;    // loop B dup (2 x 8320)
    __shared__ float sMu[NB], sRi[NB];
    __shared__ float sW1[16], sW2[16];

    const int tid = threadIdx.x;
    const int bid = blockIdx.x;
    unsigned epoch = *(volatile unsigned*)&g_sense2;

    const int arow = tid >> 3, akq = tid & 7;
    int gcol[2], gkq[2];
#pragma unroll
    for (int i = 0; i < 2; i++) { int id = tid + i * NTHR; gcol[i] = id >> 3; gkq[i] = id & 7; }
    int bcol[4], bkq[4];
#pragma unroll
    for (int i = 0; i < 4; i++) { int id = tid + i * NTHR; bcol[i] = id >> 3; bkq[i] = id & 7; }
    const int r0 = (tid >> 6) * 8;
    const int c0 = (tid & 63) * 2;        // loop: 2 cols per thread
    const int c0d = (tid & 63) * 4;       // dup-B smem float offset
    const int c0p = (tid & 63) * 4;       // proj: 4 cols per thread

    // ---- init ----
    for (int i = bid * NTHR + tid; i < 2 * NB * NM; i += NBLK * NTHR)
        g_h[i] = hidden[i];
    for (size_t i = (size_t)bid * NTHR + tid; i < (size_t)NH * NM; i += (size_t)NBLK * NTHR)
        g_cWc[i] = sk_W[i] + lc_W[i];
    for (int i = bid * NTHR + tid; i < NH; i += NBLK * NTHR)
        g_cbc[i] = sk_b[i] + lc_b[i];
    for (int i = bid * NTHR + tid; i < 2 * NM; i += NBLK * NTHR) {
        float tv = tau[i];
        float sp = (tv > 20.f) ? tv : log1pf(expf(tv));
        float tc = fminf(fmaxf(sp, 0.1f), 10.f);
        g_dcoef[i] = expf(-1.f / tc);
    }

    // ---- input projection xp = x . W_in^T ----
    for (int p = 0; p < 16; p++) {
        int task = bid + p * NBLK;
        int rowBase = (task >> 3) * 64, colBase = (task & 7) * 256;
        ull acc[4][4];
#pragma unroll
        for (int i = 0; i < 4; i++)
#pragma unroll
            for (int j = 0; j < 4; j++) acc[i][j] = 0ull;
        float4 ra, rb4[4];
        ra = *(const float4*)(x + (size_t)(rowBase + arow) * NIN + akq * 4);
#pragma unroll
        for (int i = 0; i < 4; i++)
            rb4[i] = *(const float4*)(W_in + (size_t)(colBase + bcol[i]) * NIN + bkq[i] * 4);
        STORE_AB(0);
        __syncthreads();
        for (int ku = 0; ku < 32; ku++) {
            if (ku + 1 < 32) {
                int kc = (ku + 1) * 32;
                ra = *(const float4*)(x + (size_t)(rowBase + arow) * NIN + kc + akq * 4);
#pragma unroll
                for (int i = 0; i < 4; i++)
                    rb4[i] = *(const float4*)(W_in + (size_t)(colBase + bcol[i]) * NIN + kc + bkq[i] * 4);
            }
            mm_k32(acc, sA + (ku & 1) * SA_BUF, sB + (ku & 1) * SB_BUF, r0, c0p);
            if (ku + 1 < 32) STORE_AB((ku + 1) & 1);
            __syncthreads();
        }
#pragma unroll
        for (int rp = 0; rp < 4; rp++) {
            float2 p0 = unp(acc[rp][0]), p1 = unp(acc[rp][1]);
            float2 p2 = unp(acc[rp][2]), p3 = unp(acc[rp][3]);
            float4 lo = {p0.x, p1.x, p2.x, p3.x};
            float4 hi = {p0.y, p1.y, p2.y, p3.y};
            size_t rr = (size_t)rowBase + r0 + 2 * rp;
            *(float4*)(g_xp + rr * NH + colBase + c0p) = lo;
            *(float4*)(g_xp + (rr + 1) * NH + colBase + c0p) = hi;
        }
    }
    gbarf(epoch);

    // ---- time loop ----
    for (int t = 0; t < NT; t++) {
        for (int l = 0; l < 2; l++) {
            const float* hsrc = (l == 0) ? (g_h + NB * NM) : g_h;

            // ======== phase P: 16 coltiles(128) x 8 K-splits(64), dbuf 2 slabs ========
            {
                const int ct = bid >> 3, sp = bid & 7;
                const int colBase = ct * 128, kb = sp * 64;
                const float* Wp = (l == 0) ? fb_W : g_cWc;
                ull acc[4][2];
#pragma unroll
                for (int i = 0; i < 4; i++) { acc[i][0] = 0ull; acc[i][1] = 0ull; }
                float4 ra, rb[2];
                ra = *(const float4*)(hsrc + (size_t)arow * NM + kb + akq * 4);
#pragma unroll
                for (int i = 0; i < 2; i++)
                    rb[i] = *(const float4*)(Wp + (size_t)(colBase + gcol[i]) * NM + kb + gkq[i] * 4);
                STORE_A128(0); STORE_B128(0);
                __syncthreads();
#pragma unroll
                for (int ku = 0; ku < 2; ku++) {
                    if (ku == 0) {
                        int kc = kb + 32;
                        ra = *(const float4*)(hsrc + (size_t)arow * NM + kc + akq * 4);
#pragma unroll
                        for (int i = 0; i < 2; i++)
                            rb[i] = *(const float4*)(Wp + (size_t)(colBase + gcol[i]) * NM + kc + gkq[i] * 4);
                    }
                    mm128(acc, sA2 + (ku & 1) * SA_SLAB, sBD2 + (ku & 1) * SBD_SLAB, r0, c0d);
                    if (ku == 0) { STORE_A128(1); STORE_B128(1); }
                    __syncthreads();
                }
#pragma unroll
                for (int rp = 0; rp < 4; rp++) {
                    float2 v0 = unp(acc[rp][0]), v1 = unp(acc[rp][1]);
                    int row = r0 + 2 * rp;
                    *(float2*)(g_pp + ((size_t)sp * NB + row) * NH + colBase + c0) = make_float2(v0.x, v1.x);
                    *(float2*)(g_pp + ((size_t)sp * NB + row + 1) * NH + colBase + c0) = make_float2(v0.y, v1.y);
                }
            }
            gbarf(epoch);

            // ======== phase R: reduce 8 P splits + biases + linraw + stat partials ====
            {
                const int row = bid >> 1, half = bid & 1;
                const int c = half * 1024 + tid * 2;
                float2 acc2 = {0.f, 0.f};
#pragma unroll
                for (int s = 0; s < 8; s++) {
                    float2 v = *(const float2*)(g_pp + ((size_t)s * NB + row) * NH + c);
                    acc2.x += v.x; acc2.y += v.y;
                }
                float2 val;
                if (l == 0) {
                    float fbscale = (t == 0) ? 0.f : 0.1f;
                    float2 xv = *(const float2*)(g_xp + ((size_t)row * NT + t) * NH + c);
                    float2 bi = *(const float2*)(b_in + c);
                    float2 fbb = *(const float2*)(fb_b + c);
                    val.x = xv.x + bi.x + fbscale * (acc2.x + fbb.x);
                    val.y = xv.y + bi.y + fbscale * (acc2.y + fbb.y);
                } else {
                    float2 cb = *(const float2*)(g_cbc + c);
                    val.x = acc2.x + cb.x;
                    val.y = acc2.y + cb.y;
                }
                *(float2*)(g_linraw + (size_t)row * NH + c) = val;
                float s1 = val.x + val.y;
                float s2 = val.x * val.x + val.y * val.y;
#pragma unroll
                for (int off = 16; off > 0; off >>= 1) {
                    s1 += __shfl_xor_sync(0xffffffffu, s1, off);
                    s2 += __shfl_xor_sync(0xffffffffu, s2, off);
                }
                if ((tid & 31) == 0) { sW1[tid >> 5] = s1; sW2[tid >> 5] = s2; }
                __syncthreads();
                if (tid == 0) {
                    float t1 = 0.f, t2 = 0.f;
#pragma unroll
                    for (int w = 0; w < 16; w++) { t1 += sW1[w]; t2 += sW2[w]; }
                    g_ps1[bid] = t1;
                    g_ps2[bid] = t2;
                }
            }
            gbarf(epoch);

            // ======== phase G: 112 uniform tasks of 64x128x256 (8 slabs) ========
            if (bid < 112) {
                if (tid < NB) {
                    float s1 = g_ps1[2 * tid] + g_ps1[2 * tid + 1];
                    float s2 = g_ps2[2 * tid] + g_ps2[2 * tid + 1];
                    float mu = s1 * (1.f / NH);
                    sMu[tid] = mu;
                    sRi[tid] = rsqrtf(s2 * (1.f / NH) - mu * mu + 1e-5f);
                }
                __syncthreads();
                int sp, kb, outCol, ldb;
                const float* Wb;
                if (bid < 80) {
                    int ct = bid / 10; sp = bid % 10;
                    kb = sp * 256;
                    if (ct < 4) Wb = upd_W + ((size_t)l * NM + ct * 128) * NHM;
                    else        Wb = rst_W + ((size_t)l * NM + (ct - 4) * 128) * NHM;
                    ldb = NHM; outCol = ct * 128;
                } else {
                    int b2 = bid - 80;
                    int ct = b2 >> 3; sp = b2 & 7;
                    kb = sp * 256;
                    Wb = cell_W + ((size_t)l * NM + ct * 128) * NH;
                    ldb = NH; outCol = 1024 + ct * 128;
                }
                const float* hself = g_h + l * NB * NM;
                const float* lnwl = ln_w + l * NH;
                const float* lnbl = ln_b + l * NH;
                float mu = sMu[arow], ri = sRi[arow];
                ull acc[4][2];
#pragma unroll
                for (int i = 0; i < 4; i++) { acc[i][0] = 0ull; acc[i][1] = 0ull; }
                float4 ra, rb[2];
#define G_LOAD128(KU) do { \
    int kc = kb + (KU) * 32; \
    int kg = kc + akq * 4; \
    if (kg < NH) { \
        ra = *(const float4*)(g_linraw + (size_t)arow * NH + kg); \
        float4 w = *(const float4*)(lnwl + kg); \
        float4 bb2 = *(const float4*)(lnbl + kg); \
        ra.x = (ra.x - mu) * ri * w.x + bb2.x; \
        ra.y = (ra.y - mu) * ri * w.y + bb2.y; \
        ra.z = (ra.z - mu) * ri * w.z + bb2.z; \
        ra.w = (ra.w - mu) * ri * w.w + bb2.w; \
    } else { \
        ra = *(const float4*)(hself + (size_t)arow * NM + (kg - NH)); \
    } \
    _Pragma("unroll") \
    for (int i2 = 0; i2 < 2; i2++) \
        rb[i2] = *(const float4*)(Wb + (size_t)gcol[i2] * ldb + kc + gkq[i2] * 4); \
} while (0)
                G_LOAD128(0);
                STORE_A128(0); STORE_B128(0);
                __syncthreads();
                for (int ku = 0; ku < 8; ku++) {
                    if (ku + 1 < 8) G_LOAD128(ku + 1);
                    mm128(acc, sA2 + (ku & 1) * SA_SLAB, sBD2 + (ku & 1) * SBD_SLAB, r0, c0d);
                    if (ku + 1 < 8) { STORE_A128((ku + 1) & 1); STORE_B128((ku + 1) & 1); }
                    __syncthreads();
                }
#pragma unroll
                for (int rp = 0; rp < 4; rp++) {
                    float2 v0 = unp(acc[rp][0]), v1 = unp(acc[rp][1]);
                    int row = r0 + 2 * rp;
                    *(float2*)(g_gp + ((size_t)sp * NB + row) * NG + outCol + c0) = make_float2(v0.x, v1.x);
                    *(float2*)(g_gp + ((size_t)sp * NB + row + 1) * NG + outCol + c0) = make_float2(v0.y, v1.y);
                }
            }
            gbarf(epoch);

            // ======== phase C: reduce G splits + gates + mem-LN + write ========
            if (bid < NB) {
                int b = bid, m = tid;
                float* hl = g_h + l * NB * NM;
                float su = 0.f, sr = 0.f, sc = 0.f;
#pragma unroll
                for (int s = 0; s < 10; s++) {
                    size_t base = ((size_t)s * NB + b) * NG;
                    su += g_gp[base + m];
                    sr += g_gp[base + 512 + m];
                }
#pragma unroll
                for (int s = 0; s < 8; s++)
                    sc += g_gp[((size_t)s * NB + b) * NG + 1024 + m];
                int lm = l * NM + m;
                float u = 1.f / (1.f + expf(-(su + upd_b[lm])));
                float r = 1.f / (1.f + expf(-(sr + rst_b[lm])));
                float cand = tanhf(sc + cell_b[lm]);
                float d = g_dcoef[lm] * u;
                float hp = hl[(size_t)b * NM + m];
                float hn = d * (hp * r) + (1.f - d) * cand;
                float s1 = hn, s2 = hn * hn;
#pragma unroll
                for (int off = 16; off > 0; off >>= 1) {
                    s1 += __shfl_xor_sync(0xffffffffu, s1, off);
                    s2 += __shfl_xor_sync(0xffffffffu, s2, off);
                }
                if ((tid & 31) == 0) { sW1[tid >> 5] = s1; sW2[tid >> 5] = s2; }
                __syncthreads();
                if (tid == 0) {
                    float t1 = 0.f, t2 = 0.f;
#pragma unroll
                    for (int w = 0; w < 16; w++) { t1 += sW1[w]; t2 += sW2[w]; }
                    float mu = t1 * (1.f / NM);
                    sMu[0] = mu;
                    sRi[0] = rsqrtf(t2 * (1.f / NM) - mu * mu + 1e-5f);
                }
                __syncthreads();
                float v = (hn - sMu[0]) * sRi[0] * mn_w[lm] + mn_b[lm];
                hl[(size_t)b * NM + m] = v;
                if (l == 1) out[((size_t)b * NT + t) * NM + m] = v;
            }
            gbarf(epoch);
        }
    }

    // ---- final hidden states hT appended after outs [B,T,M] ----
    for (int i = bid * NTHR + tid; i < 2 * NB * NM; i += NBLK * NTHR)
        out[(size_t)NB * NT * NM + i] = g_h[i];
}

extern "C" void kernel_launch(void* const* d_in, const int* in_sizes, int n_in,
                              void* d_out, int out_size)
{
    const float* x      = (const float*)d_in[0];
    const float* hidden = (const float*)d_in[1];
    const float* W_in   = (const float*)d_in[2];
    const float* b_in   = (const float*)d_in[3];
    const float* cell_W = (const float*)d_in[4];
    const float* cell_b = (const float*)d_in[5];
    const float* upd_W  = (const float*)d_in[6];
    const float* upd_b  = (const float*)d_in[7];
    const float* rst_W  = (const float*)d_in[8];
    const float* rst_b  = (const float*)d_in[9];
    const float* tau    = (const float*)d_in[10];
    const float* lc_W   = (const float*)d_in[11];
    const float* lc_b   = (const float*)d_in[12];
    const float* sk_W   = (const float*)d_in[13];
    const float* sk_b   = (const float*)d_in[14];
    const float* fb_W   = (const float*)d_in[15];
    const float* fb_b   = (const float*)d_in[16];
    const float* ln_w   = (const float*)d_in[17];
    const float* ln_b   = (const float*)d_in[18];
    const float* mn_w   = (const float*)d_in[19];
    const float* mn_b   = (const float*)d_in[20];
    float* out = (float*)d_out;

    cudaFuncSetAttribute(ltc_all, cudaFuncAttributeMaxDynamicSharedMemorySize, DYN_BYTES);
    ltc_all<<<NBLK, NTHR, DYN_BYTES>>>(x, hidden, W_in, b_in, cell_W, cell_b,
                                       upd_W, upd_b, rst_W, rst_b, tau,
                                       lc_W, lc_b, sk_W, sk_b, fb_W, fb_b,
                                       ln_w, ln_b, mn_w, mn_b, out);
}

// round 8
// speedup vs baseline: 1.0054x; 1.0054x over previous
#include <cuda_runtime.h>
#include <cstddef>

typedef unsigned long long ull;

#define NB 64
#define NT 256
#define NIN 1024
#define NH 2048
#define NM 512
#define NHM 2560
#define NG 1536
#define NBLK 128
#define NTHR 512

// proj (N=256) tile layout
#define SA_STRIDE 96
#define SB_STRIDE 288
#define SA_BUF 3072
#define SB_BUF 9216
// loop (N=128, dup-B) tile layout
#define SA_STR 96
#define SBD_STR 260
#define SA_SLAB 3072
#define SBD_SLAB 8320
#define DYN_BYTES 98304

// ---------------- device scratch ----------------
__device__ float g_xp[(size_t)NB * NT * NH];
__device__ float g_h[2 * NB * NM];
__device__ float g_linraw[NB * NH];
__device__ float g_pp[(size_t)8 * NB * NH];    // P partials (8 splits)
__device__ float g_ps1[NBLK];
__device__ float g_ps2[NBLK];
__device__ float g_gp[(size_t)10 * NB * NG];   // G partials (<=10 splits)
__device__ float g_cWc[(size_t)NH * NM];
__device__ float g_cbc[NH];
__device__ float g_dcoef[2 * NM];
__device__ unsigned g_flags[NBLK];             // zero-init
__device__ unsigned g_sense2;                  // zero-init

// ---------------- f32x2 helpers ----------------
__device__ __forceinline__ void fma2(ull &d, ull a, ull b) {
    asm("fma.rn.f32x2 %0, %1, %2, %0;" : "+l"(d) : "l"(a), "l"(b));
}
__device__ __forceinline__ ull dup2(float x) {
    ull r; asm("mov.b64 %0, {%1, %1};" : "=l"(r) : "f"(x)); return r;
}
__device__ __forceinline__ float2 unp(ull v) {
    float2 r; asm("mov.b64 {%0, %1}, %2;" : "=f"(r.x), "=f"(r.y) : "l"(v)); return r;
}

// ---------------- flag-based grid barrier (no atomics) ----------------
__device__ __forceinline__ void gbarf(unsigned &epoch) {
    __syncthreads();
    epoch++;
    if (blockIdx.x == 0) {
        int t = threadIdx.x;
        if (t >= 1 && t < NBLK) {
            unsigned v;
            do {
                asm volatile("ld.global.acquire.gpu.u32 %0, [%1];"
                             : "=r"(v) : "l"(g_flags + t) : "memory");
            } while ((int)(v - epoch) < 0);
        }
        __syncthreads();
        if (threadIdx.x == 0) {
            __threadfence();
            asm volatile("st.global.release.gpu.u32 [%0], %1;"
                         :: "l"(&g_sense2), "r"(epoch) : "memory");
        }
    } else {
        if (threadIdx.x == 0) {
            __threadfence();
            asm volatile("st.global.release.gpu.u32 [%0], %1;"
                         :: "l"(g_flags + blockIdx.x), "r"(epoch) : "memory");
            unsigned v;
            do {
                asm volatile("ld.global.acquire.gpu.u32 %0, [%1];"
                             : "=r"(v) : "l"(&g_sense2) : "memory");
            } while ((int)(v - epoch) < 0);
        }
    }
    __syncthreads();
}

// ---------------- proj inner: 64x256 tile, acc[4][4] ----------------
__device__ __forceinline__ void mm_k32(ull acc[4][4], const float* sAb, const float* sBb,
                                       int r0, int c0) {
#pragma unroll 8
    for (int k = 0; k < 32; k++) {
        int rot = k & 28;
        const float* ar = sAb + k * SA_STRIDE + rot + r0;
        ull a0 = *(const ull*)(ar);
        ull a1 = *(const ull*)(ar + 2);
        ull a2 = *(const ull*)(ar + 4);
        ull a3 = *(const ull*)(ar + 6);
        float4 bf = *(const float4*)(sBb + k * SB_STRIDE + rot + c0);
        ull b0 = dup2(bf.x), b1 = dup2(bf.y), b2 = dup2(bf.z), b3 = dup2(bf.w);
        fma2(acc[0][0], a0, b0); fma2(acc[0][1], a0, b1); fma2(acc[0][2], a0, b2); fma2(acc[0][3], a0, b3);
        fma2(acc[1][0], a1, b0); fma2(acc[1][1], a1, b1); fma2(acc[1][2], a1, b2); fma2(acc[1][3], a1, b3);
        fma2(acc[2][0], a2, b0); fma2(acc[2][1], a2, b1); fma2(acc[2][2], a2, b2); fma2(acc[2][3], a2, b3);
        fma2(acc[3][0], a3, b0); fma2(acc[3][1], a3, b1); fma2(acc[3][2], a3, b2); fma2(acc[3][3], a3, b3);
    }
}

// ---------------- loop inner: 64x128 tile, dup-B, acc[4][2] ----------------
__device__ __forceinline__ void mm128(ull acc[4][2], const float* sAb, const float* sBb,
                                      int r0, int c0d) {
#pragma unroll 8
    for (int k = 0; k < 32; k++) {
        int rot = k & 28;
        const float* ar = sAb + k * SA_STR + rot + r0;
        ull a0 = *(const ull*)(ar);
        ull a1 = *(const ull*)(ar + 2);
        ull a2 = *(const ull*)(ar + 4);
        ull a3 = *(const ull*)(ar + 6);
        ulonglong2 bb = *(const ulonglong2*)(sBb + k * SBD_STR + c0d);
        fma2(acc[0][0], a0, bb.x); fma2(acc[0][1], a0, bb.y);
        fma2(acc[1][0], a1, bb.x); fma2(acc[1][1], a1, bb.y);
        fma2(acc[2][0], a2, bb.x); fma2(acc[2][1], a2, bb.y);
        fma2(acc[3][0], a3, bb.x); fma2(acc[3][1], a3, bb.y);
    }
}

// proj stores (N=256, non-dup)
#define STORE_AB(bsel) do { \
    float* dA = sA + (bsel) * SA_BUF + (akq * 4) * SA_STRIDE + akq * 4 + arow; \
    dA[0] = ra.x; dA[SA_STRIDE] = ra.y; dA[2 * SA_STRIDE] = ra.z; dA[3 * SA_STRIDE] = ra.w; \
    _Pragma("unroll") \
    for (int i2 = 0; i2 < 4; i2++) { \
        float* dB = sB + (bsel) * SB_BUF + (bkq[i2] * 4) * SB_STRIDE + bkq[i2] * 4 + bcol[i2]; \
        dB[0] = rb4[i2].x; dB[SB_STRIDE] = rb4[i2].y; \
        dB[2 * SB_STRIDE] = rb4[i2].z; dB[3 * SB_STRIDE] = rb4[i2].w; \
    } \
} while (0)

// loop stores (N=128, dup-B)
#define STORE_A128(bsel) do { \
    float* dA = sA2 + (bsel) * SA_SLAB + (akq * 4) * SA_STR + akq * 4 + arow; \
    dA[0] = ra.x; dA[SA_STR] = ra.y; dA[2 * SA_STR] = ra.z; dA[3 * SA_STR] = ra.w; \
} while (0)

#define STORE_B128(bsel) do { \
    _Pragma("unroll") \
    for (int i2 = 0; i2 < 2; i2++) { \
        float* dB = sBD2 + (bsel) * SBD_SLAB + (gkq[i2] * 4) * SBD_STR + 2 * gcol[i2]; \
        *(float2*)(dB)                = make_float2(rb[i2].x, rb[i2].x); \
        *(float2*)(dB + SBD_STR)      = make_float2(rb[i2].y, rb[i2].y); \
        *(float2*)(dB + 2 * SBD_STR)  = make_float2(rb[i2].z, rb[i2].z); \
        *(float2*)(dB + 3 * SBD_STR)  = make_float2(rb[i2].w, rb[i2].w); \
    } \
} while (0)

__global__ void __launch_bounds__(NTHR)
ltc_all(const float* __restrict__ x,      const float* __restrict__ hidden,
        const float* __restrict__ W_in,   const float* __restrict__ b_in,
        const float* __restrict__ cell_W, const float* __restrict__ cell_b,
        const float* __restrict__ upd_W,  const float* __restrict__ upd_b,
        const float* __restrict__ rst_W,  const float* __restrict__ rst_b,
        const float* __restrict__ tau,
        const float* __restrict__ lc_W,   const float* __restrict__ lc_b,
        const float* __restrict__ sk_W,   const float* __restrict__ sk_b,
        const float* __restrict__ fb_W,   const float* __restrict__ fb_b,
        const float* __restrict__ ln_w,   const float* __restrict__ ln_b,
        const float* __restrict__ mn_w,   const float* __restrict__ mn_b,
        float* __restrict__ out)
{
    extern __shared__ float dyn[];
    float* sA   = dyn;                  // proj A (2 x 3072)
    float* sB   = dyn + 2 * SA_BUF;     // proj B (2 x 9216)
    float* sA2  = dyn;                  // loop A (2 x 3072)
    float* sBD2 = dyn + 2 * SA_SLAB;    // loop B dup (2 x 8320)
    __shared__ float sMu[NB], sRi[NB];
    __shared__ float sW1[16], sW2[16];

    const int tid = threadIdx.x;
    const int bid = blockIdx.x;
    unsigned epoch = *(volatile unsigned*)&g_sense2;

    const int arow = tid >> 3, akq = tid & 7;
    int gcol[2], gkq[2];
#pragma unroll
    for (int i = 0; i < 2; i++) { int id = tid + i * NTHR; gcol[i] = id >> 3; gkq[i] = id & 7; }
    int bcol[4], bkq[4];
#pragma unroll
    for (int i = 0; i < 4; i++) { int id = tid + i * NTHR; bcol[i] = id >> 3; bkq[i] = id & 7; }
    const int r0 = (tid >> 6) * 8;
    const int c0 = (tid & 63) * 2;        // loop: 2 cols per thread
    const int c0d = (tid & 63) * 4;       // dup-B smem float offset
    const int c0p = (tid & 63) * 4;       // proj: 4 cols per thread

    // ---- init ----
    for (int i = bid * NTHR + tid; i < 2 * NB * NM; i += NBLK * NTHR)
        g_h[i] = hidden[i];
    for (size_t i = (size_t)bid * NTHR + tid; i < (size_t)NH * NM; i += (size_t)NBLK * NTHR)
        g_cWc[i] = sk_W[i] + lc_W[i];
    for (int i = bid * NTHR + tid; i < NH; i += NBLK * NTHR)
        g_cbc[i] = sk_b[i] + lc_b[i];
    for (int i = bid * NTHR + tid; i < 2 * NM; i += NBLK * NTHR) {
        float tv = tau[i];
        float sp = (tv > 20.f) ? tv : log1pf(expf(tv));
        float tc = fminf(fmaxf(sp, 0.1f), 10.f);
        g_dcoef[i] = expf(-1.f / tc);
    }

    // ---- input projection xp = x . W_in^T ----
    for (int p = 0; p < 16; p++) {
        int task = bid + p * NBLK;
        int rowBase = (task >> 3) * 64, colBase = (task & 7) * 256;
        ull acc[4][4];
#pragma unroll
        for (int i = 0; i < 4; i++)
#pragma unroll
            for (int j = 0; j < 4; j++) acc[i][j] = 0ull;
        float4 ra, rb4[4];
        ra = *(const float4*)(x + (size_t)(rowBase + arow) * NIN + akq * 4);
#pragma unroll
        for (int i = 0; i < 4; i++)
            rb4[i] = *(const float4*)(W_in + (size_t)(colBase + bcol[i]) * NIN + bkq[i] * 4);
        STORE_AB(0);
        __syncthreads();
        for (int ku = 0; ku < 32; ku++) {
            if (ku + 1 < 32) {
                int kc = (ku + 1) * 32;
                ra = *(const float4*)(x + (size_t)(rowBase + arow) * NIN + kc + akq * 4);
#pragma unroll
                for (int i = 0; i < 4; i++)
                    rb4[i] = *(const float4*)(W_in + (size_t)(colBase + bcol[i]) * NIN + kc + bkq[i] * 4);
            }
            mm_k32(acc, sA + (ku & 1) * SA_BUF, sB + (ku & 1) * SB_BUF, r0, c0p);
            if (ku + 1 < 32) STORE_AB((ku + 1) & 1);
            __syncthreads();
        }
#pragma unroll
        for (int rp = 0; rp < 4; rp++) {
            float2 p0 = unp(acc[rp][0]), p1 = unp(acc[rp][1]);
            float2 p2 = unp(acc[rp][2]), p3 = unp(acc[rp][3]);
            float4 lo = {p0.x, p1.x, p2.x, p3.x};
            float4 hi = {p0.y, p1.y, p2.y, p3.y};
            size_t rr = (size_t)rowBase + r0 + 2 * rp;
            *(float4*)(g_xp + rr * NH + colBase + c0p) = lo;
            *(float4*)(g_xp + (rr + 1) * NH + colBase + c0p) = hi;
        }
    }
    gbarf(epoch);

    // ---- time loop ----
    for (int t = 0; t < NT; t++) {
        for (int l = 0; l < 2; l++) {
            const float* hsrc = (l == 0) ? (g_h + NB * NM) : g_h;

            // ======== phase P: 16 coltiles(128) x 8 K-splits(64), dbuf 2 slabs ========
            {
                const int ct = bid >> 3, sp = bid & 7;
                const int colBase = ct * 128, kb = sp * 64;
                const float* Wp = (l == 0) ? fb_W : g_cWc;
                ull acc[4][2];
#pragma unroll
                for (int i = 0; i < 4; i++) { acc[i][0] = 0ull; acc[i][1] = 0ull; }
                float4 ra, rb[2];
                ra = *(const float4*)(hsrc + (size_t)arow * NM + kb + akq * 4);
#pragma unroll
                for (int i = 0; i < 2; i++)
                    rb[i] = *(const float4*)(Wp + (size_t)(colBase + gcol[i]) * NM + kb + gkq[i] * 4);
                STORE_A128(0); STORE_B128(0);
                __syncthreads();
#pragma unroll
                for (int ku = 0; ku < 2; ku++) {
                    if (ku == 0) {
                        int kc = kb + 32;
                        ra = *(const float4*)(hsrc + (size_t)arow * NM + kc + akq * 4);
#pragma unroll
                        for (int i = 0; i < 2; i++)
                            rb[i] = *(const float4*)(Wp + (size_t)(colBase + gcol[i]) * NM + kc + gkq[i] * 4);
                    }
                    mm128(acc, sA2 + (ku & 1) * SA_SLAB, sBD2 + (ku & 1) * SBD_SLAB, r0, c0d);
                    if (ku == 0) { STORE_A128(1); STORE_B128(1); }
                    __syncthreads();
                }
#pragma unroll
                for (int rp = 0; rp < 4; rp++) {
                    float2 v0 = unp(acc[rp][0]), v1 = unp(acc[rp][1]);
                    int row = r0 + 2 * rp;
                    *(float2*)(g_pp + ((size_t)sp * NB + row) * NH + colBase + c0) = make_float2(v0.x, v1.x);
                    *(float2*)(g_pp + ((size_t)sp * NB + row + 1) * NH + colBase + c0) = make_float2(v0.y, v1.y);
                }
            }
            gbarf(epoch);

            // ======== phase R: reduce 8 P splits + biases + linraw + stat partials ====
            {
                const int row = bid >> 1, half = bid & 1;
                const int c = half * 1024 + tid * 2;
                float2 acc2 = {0.f, 0.f};
#pragma unroll
                for (int s = 0; s < 8; s++) {
                    float2 v = *(const float2*)(g_pp + ((size_t)s * NB + row) * NH + c);
                    acc2.x += v.x; acc2.y += v.y;
                }
                float2 val;
                if (l == 0) {
                    float fbscale = (t == 0) ? 0.f : 0.1f;
                    float2 xv = *(const float2*)(g_xp + ((size_t)row * NT + t) * NH + c);
                    float2 bi = *(const float2*)(b_in + c);
                    float2 fbb = *(const float2*)(fb_b + c);
                    val.x = xv.x + bi.x + fbscale * (acc2.x + fbb.x);
                    val.y = xv.y + bi.y + fbscale * (acc2.y + fbb.y);
                } else {
                    float2 cb = *(const float2*)(g_cbc + c);
                    val.x = acc2.x + cb.x;
                    val.y = acc2.y + cb.y;
                }
                *(float2*)(g_linraw + (size_t)row * NH + c) = val;
                float s1 = val.x + val.y;
                float s2 = val.x * val.x + val.y * val.y;
#pragma unroll
                for (int off = 16; off > 0; off >>= 1) {
                    s1 += __shfl_xor_sync(0xffffffffu, s1, off);
                    s2 += __shfl_xor_sync(0xffffffffu, s2, off);
                }
                if ((tid & 31) == 0) { sW1[tid >> 5] = s1; sW2[tid >> 5] = s2; }
                __syncthreads();
                if (tid == 0) {
                    float t1 = 0.f, t2 = 0.f;
#pragma unroll
                    for (int w = 0; w < 16; w++) { t1 += sW1[w]; t2 += sW2[w]; }
                    g_ps1[bid] = t1;
                    g_ps2[bid] = t2;
                }
            }
            gbarf(epoch);

            // ======== phase G: 112 uniform tasks of 64x128x256 (8 slabs) ========
            if (bid < 112) {
                if (tid < NB) {
                    float s1 = g_ps1[2 * tid] + g_ps1[2 * tid + 1];
                    float s2 = g_ps2[2 * tid] + g_ps2[2 * tid + 1];
                    float mu = s1 * (1.f / NH);
                    sMu[tid] = mu;
                    sRi[tid] = rsqrtf(s2 * (1.f / NH) - mu * mu + 1e-5f);
                }
                __syncthreads();
                int sp, kb, outCol, ldb;
                const float* Wb;
                if (bid < 80) {
                    int ct = bid / 10; sp = bid % 10;
                    kb = sp * 256;
                    if (ct < 4) Wb = upd_W + ((size_t)l * NM + ct * 128) * NHM;
                    else        Wb = rst_W + ((size_t)l * NM + (ct - 4) * 128) * NHM;
                    ldb = NHM; outCol = ct * 128;
                } else {
                    int b2 = bid - 80;
                    int ct = b2 >> 3; sp = b2 & 7;
                    kb = sp * 256;
                    Wb = cell_W + ((size_t)l * NM + ct * 128) * NH;
                    ldb = NH; outCol = 1024 + ct * 128;
                }
                const float* hself = g_h + l * NB * NM;
                const float* lnwl = ln_w + l * NH;
                const float* lnbl = ln_b + l * NH;
                float mu = sMu[arow], ri = sRi[arow];
                ull acc[4][2];
#pragma unroll
                for (int i = 0; i < 4; i++) { acc[i][0] = 0ull; acc[i][1] = 0ull; }
                float4 ra, rb[2];
#define G_LOAD128(KU) do { \
    int kc = kb + (KU) * 32; \
    int kg = kc + akq * 4; \
    if (kg < NH) { \
        ra = *(const float4*)(g_linraw + (size_t)arow * NH + kg); \
        float4 w = *(const float4*)(lnwl + kg); \
        float4 bb2 = *(const float4*)(lnbl + kg); \
        ra.x = (ra.x - mu) * ri * w.x + bb2.x; \
        ra.y = (ra.y - mu) * ri * w.y + bb2.y; \
        ra.z = (ra.z - mu) * ri * w.z + bb2.z; \
        ra.w = (ra.w - mu) * ri * w.w + bb2.w; \
    } else { \
        ra = *(const float4*)(hself + (size_t)arow * NM + (kg - NH)); \
    } \
    _Pragma("unroll") \
    for (int i2 = 0; i2 < 2; i2++) \
        rb[i2] = *(const float4*)(Wb + (size_t)gcol[i2] * ldb + kc + gkq[i2] * 4); \
} while (0)
                G_LOAD128(0);
                STORE_A128(0); STORE_B128(0);
                __syncthreads();
                for (int ku = 0; ku < 8; ku++) {
                    if (ku + 1 < 8) G_LOAD128(ku + 1);
                    mm128(acc, sA2 + (ku & 1) * SA_SLAB, sBD2 + (ku & 1) * SBD_SLAB, r0, c0d);
                    if (ku + 1 < 8) { STORE_A128((ku + 1) & 1); STORE_B128((ku + 1) & 1); }
                    __syncthreads();
                }
#pragma unroll
                for (int rp = 0; rp < 4; rp++) {
                    float2 v0 = unp(acc[rp][0]), v1 = unp(acc[rp][1]);
                    int row = r0 + 2 * rp;
                    *(float2*)(g_gp + ((size_t)sp * NB + row) * NG + outCol + c0) = make_float2(v0.x, v1.x);
                    *(float2*)(g_gp + ((size_t)sp * NB + row + 1) * NG + outCol + c0) = make_float2(v0.y, v1.y);
                }
            }
            gbarf(epoch);

            // ======== phase C: reduce G splits + gates + mem-LN + write ========
            if (bid < NB) {
                int b = bid, m = tid;
                float* hl = g_h + l * NB * NM;
                float su = 0.f, sr = 0.f, sc = 0.f;
#pragma unroll
                for (int s = 0; s < 10; s++) {
                    size_t base = ((size_t)s * NB + b) * NG;
                    su += g_gp[base + m];
                    sr += g_gp[base + 512 + m];
                }
#pragma unroll
                for (int s = 0; s < 8; s++)
                    sc += g_gp[((size_t)s * NB + b) * NG + 1024 + m];
                int lm = l * NM + m;
                float u = 1.f / (1.f + expf(-(su + upd_b[lm])));
                float r = 1.f / (1.f + expf(-(sr + rst_b[lm])));
                float cand = tanhf(sc + cell_b[lm]);
                float d = g_dcoef[lm] * u;
                float hp = hl[(size_t)b * NM + m];
                float hn = d * (hp * r) + (1.f - d) * cand;
                float s1 = hn, s2 = hn * hn;
#pragma unroll
                for (int off = 16; off > 0; off >>= 1) {
                    s1 += __shfl_xor_sync(0xffffffffu, s1, off);
                    s2 += __shfl_xor_sync(0xffffffffu, s2, off);
                }
                if ((tid & 31) == 0) { sW1[tid >> 5] = s1; sW2[tid >> 5] = s2; }
                __syncthreads();
                if (tid == 0) {
                    float t1 = 0.f, t2 = 0.f;
#pragma unroll
                    for (int w = 0; w < 16; w++) { t1 += sW1[w]; t2 += sW2[w]; }
                    float mu = t1 * (1.f / NM);
                    sMu[0] = mu;
                    sRi[0] = rsqrtf(t2 * (1.f / NM) - mu * mu + 1e-5f);
                }
                __syncthreads();
                float v = (hn - sMu[0]) * sRi[0] * mn_w[lm] + mn_b[lm];
                hl[(size_t)b * NM + m] = v;
                if (l == 1) out[((size_t)b * NT + t) * NM + m] = v;
            }
            gbarf(epoch);
        }
    }

    // ---- final hidden states hT appended after outs [B,T,M] ----
    for (int i = bid * NTHR + tid; i < 2 * NB * NM; i += NBLK * NTHR)
        out[(size_t)NB * NT * NM + i] = g_h[i];
}

extern "C" void kernel_launch(void* const* d_in, const int* in_sizes, int n_in,
                              void* d_out, int out_size)
{
    const float* x      = (const float*)d_in[0];
    const float* hidden = (const float*)d_in[1];
    const float* W_in   = (const float*)d_in[2];
    const float* b_in   = (const float*)d_in[3];
    const float* cell_W = (const float*)d_in[4];
    const float* cell_b = (const float*)d_in[5];
    const float* upd_W  = (const float*)d_in[6];
    const float* upd_b  = (const float*)d_in[7];
    const float* rst_W  = (const float*)d_in[8];
    const float* rst_b  = (const float*)d_in[9];
    const float* tau    = (const float*)d_in[10];
    const float* lc_W   = (const float*)d_in[11];
    const float* lc_b   = (const float*)d_in[12];
    const float* sk_W   = (const float*)d_in[13];
    const float* sk_b   = (const float*)d_in[14];
    const float* fb_W   = (const float*)d_in[15];
    const float* fb_b   = (const float*)d_in[16];
    const float* ln_w   = (const float*)d_in[17];
    const float* ln_b   = (const float*)d_in[18];
    const float* mn_w   = (const float*)d_in[19];
    const float* mn_b   = (const float*)d_in[20];
    float* out = (float*)d_out;

    cudaFuncSetAttribute(ltc_all, cudaFuncAttributeMaxDynamicSharedMemorySize, DYN_BYTES);
    ltc_all<<<NBLK, NTHR, DYN_BYTES>>>(x, hidden, W_in, b_in, cell_W, cell_b,
                                       upd_W, upd_b, rst_W, rst_b, tau,
                                       lc_W, lc_b, sk_W, sk_b, fb_W, fb_b,
                                       ln_w, ln_b, mn_w, mn_b, out);
}

// round 9
// speedup vs baseline: 1.3971x; 1.3897x over previous
#include <cuda_runtime.h>
#include <cstddef>

typedef unsigned long long ull;

#define NB 64
#define NT 256
#define NIN 1024
#define NH 2048
#define NM 512
#define NHM 2560
#define NG 1536
#define NBLK 128
#define NTHR 512

#define SA_STRIDE 96
#define SB_STRIDE 288
#define SA_BUF 3072
#define SB_BUF 9216
#define DYN_BYTES 98304

// ---------------- device scratch ----------------
__device__ float g_xp[(size_t)NB * NT * NH];
__device__ float g_h[2 * NB * NM];
__device__ float g_linraw[NB * NH];
__device__ float g_pp[(size_t)16 * NB * NH];   // P gemm split partials
__device__ float g_ps1[NBLK];                  // per (row,half) stat partials
__device__ float g_ps2[NBLK];
__device__ float g_gp[(size_t)24 * NB * NG];   // G gemm split partials
__device__ float g_cWc[(size_t)NH * NM];       // sk_W + lc_W
__device__ float g_cbc[NH];                    // sk_b + lc_b
__device__ float g_dcoef[2 * NM];              // exp(-1/clip(softplus(tau)))
__device__ unsigned g_flags[NBLK];             // zero-init
__device__ unsigned g_sense2;                  // zero-init

// ---------------- f32x2 helpers ----------------
__device__ __forceinline__ void fma2(ull &d, ull a, ull b) {
    asm("fma.rn.f32x2 %0, %1, %2, %0;" : "+l"(d) : "l"(a), "l"(b));
}
__device__ __forceinline__ ull dup2(float x) {
    ull r; asm("mov.b64 %0, {%1, %1};" : "=l"(r) : "f"(x)); return r;
}
__device__ __forceinline__ float2 unp(ull v) {
    float2 r; asm("mov.b64 {%0, %1}, %2;" : "=f"(r.x), "=f"(r.y) : "l"(v)); return r;
}

// ---------------- flag-based grid barrier (no atomics) ----------------
__device__ __forceinline__ void gbarf(unsigned &epoch) {
    __syncthreads();
    epoch++;
    if (blockIdx.x == 0) {
        int t = threadIdx.x;
        if (t >= 1 && t < NBLK) {
            unsigned v;
            do {
                asm volatile("ld.global.acquire.gpu.u32 %0, [%1];"
                             : "=r"(v) : "l"(g_flags + t) : "memory");
            } while ((int)(v - epoch) < 0);
        }
        __syncthreads();
        if (threadIdx.x == 0) {
            asm volatile("st.global.release.gpu.u32 [%0], %1;"
                         :: "l"(&g_sense2), "r"(epoch) : "memory");
        }
    } else {
        if (threadIdx.x == 0) {
            asm volatile("st.global.release.gpu.u32 [%0], %1;"
                         :: "l"(g_flags + blockIdx.x), "r"(epoch) : "memory");
            unsigned v;
            do {
                asm volatile("ld.global.acquire.gpu.u32 %0, [%1];"
                             : "=r"(v) : "l"(&g_sense2) : "memory");
            } while ((int)(v - epoch) < 0);
        }
    }
    __syncthreads();
}

// ---------------- 64x256 tile inner: 32 k-steps, 8 rows x 4 cols per thread --------
__device__ __forceinline__ void mm_k32(ull acc[4][4], const float* sAb, const float* sBb,
                                       int r0, int c0) {
#pragma unroll 8
    for (int k = 0; k < 32; k++) {
        int rot = k & 28;
        const float* ar = sAb + k * SA_STRIDE + rot + r0;
        ull a0 = *(const ull*)(ar);
        ull a1 = *(const ull*)(ar + 2);
        ull a2 = *(const ull*)(ar + 4);
        ull a3 = *(const ull*)(ar + 6);
        float4 bf = *(const float4*)(sBb + k * SB_STRIDE + rot + c0);
        ull b0 = dup2(bf.x), b1 = dup2(bf.y), b2 = dup2(bf.z), b3 = dup2(bf.w);
        fma2(acc[0][0], a0, b0); fma2(acc[0][1], a0, b1); fma2(acc[0][2], a0, b2); fma2(acc[0][3], a0, b3);
        fma2(acc[1][0], a1, b0); fma2(acc[1][1], a1, b1); fma2(acc[1][2], a1, b2); fma2(acc[1][3], a1, b3);
        fma2(acc[2][0], a2, b0); fma2(acc[2][1], a2, b1); fma2(acc[2][2], a2, b2); fma2(acc[2][3], a2, b3);
        fma2(acc[3][0], a3, b0); fma2(acc[3][1], a3, b1); fma2(acc[3][2], a3, b2); fma2(acc[3][3], a3, b3);
    }
}

#define STORE_AB(bsel) do { \
    float* dA = sA + (bsel) * SA_BUF + (akq * 4) * SA_STRIDE + akq * 4 + arow; \
    dA[0] = ra.x; dA[SA_STRIDE] = ra.y; dA[2 * SA_STRIDE] = ra.z; dA[3 * SA_STRIDE] = ra.w; \
    _Pragma("unroll") \
    for (int i2 = 0; i2 < 4; i2++) { \
        float* dB = sB + (bsel) * SB_BUF + (bkq[i2] * 4) * SB_STRIDE + bkq[i2] * 4 + bcol[i2]; \
        dB[0] = rb[i2].x; dB[SB_STRIDE] = rb[i2].y; \
        dB[2 * SB_STRIDE] = rb[i2].z; dB[3 * SB_STRIDE] = rb[i2].w; \
    } \
} while (0)

__global__ void __launch_bounds__(NTHR)
ltc_all(const float* __restrict__ x,      const float* __restrict__ hidden,
        const float* __restrict__ W_in,   const float* __restrict__ b_in,
        const float* __restrict__ cell_W, const float* __restrict__ cell_b,
        const float* __restrict__ upd_W,  const float* __restrict__ upd_b,
        const float* __restrict__ rst_W,  const float* __restrict__ rst_b,
        const float* __restrict__ tau,
        const float* __restrict__ lc_W,   const float* __restrict__ lc_b,
        const float* __restrict__ sk_W,   const float* __restrict__ sk_b,
        const float* __restrict__ fb_W,   const float* __restrict__ fb_b,
        const float* __restrict__ ln_w,   const float* __restrict__ ln_b,
        const float* __restrict__ mn_w,   const float* __restrict__ mn_b,
        float* __restrict__ out)
{
    extern __shared__ float dyn[];
    float* sA = dyn;
    float* sB = dyn + 2 * SA_BUF;
    __shared__ float sMu[NB], sRi[NB];
    __shared__ float sW1[16], sW2[16];

    const int tid = threadIdx.x;
    const int bid = blockIdx.x;
    unsigned epoch = *(volatile unsigned*)&g_sense2;

    const int arow = tid >> 3, akq = tid & 7;
    int bcol[4], bkq[4];
#pragma unroll
    for (int i = 0; i < 4; i++) { int id = tid + i * NTHR; bcol[i] = id >> 3; bkq[i] = id & 7; }
    const int r0 = (tid >> 6) * 8;
    const int c0 = (tid & 63) * 4;

    // ---- init: h copy, precompute cWc/cbc/dcoef, input projection ----
    for (int i = bid * NTHR + tid; i < 2 * NB * NM; i += NBLK * NTHR)
        g_h[i] = hidden[i];
    for (size_t i = (size_t)bid * NTHR + tid; i < (size_t)NH * NM; i += (size_t)NBLK * NTHR)
        g_cWc[i] = sk_W[i] + lc_W[i];
    for (int i = bid * NTHR + tid; i < NH; i += NBLK * NTHR)
        g_cbc[i] = sk_b[i] + lc_b[i];
    for (int i = bid * NTHR + tid; i < 2 * NM; i += NBLK * NTHR) {
        float tv = tau[i];
        float sp = (tv > 20.f) ? tv : log1pf(expf(tv));
        float tc = fminf(fmaxf(sp, 0.1f), 10.f);
        g_dcoef[i] = expf(-1.f / tc);
    }

    // input projection: xp = x . W_in^T  (2048 tasks of 64x256, dbuf pipeline)
    for (int p = 0; p < 16; p++) {
        int task = bid + p * NBLK;
        int rowBase = (task >> 3) * 64, colBase = (task & 7) * 256;
        ull acc[4][4];
#pragma unroll
        for (int i = 0; i < 4; i++)
#pragma unroll
            for (int j = 0; j < 4; j++) acc[i][j] = 0ull;
        float4 ra, rb[4];
        ra = *(const float4*)(x + (size_t)(rowBase + arow) * NIN + akq * 4);
#pragma unroll
        for (int i = 0; i < 4; i++)
            rb[i] = *(const float4*)(W_in + (size_t)(colBase + bcol[i]) * NIN + bkq[i] * 4);
        STORE_AB(0);
        __syncthreads();
        for (int ku = 0; ku < 32; ku++) {
            if (ku + 1 < 32) {
                int kc = (ku + 1) * 32;
                ra = *(const float4*)(x + (size_t)(rowBase + arow) * NIN + kc + akq * 4);
#pragma unroll
                for (int i = 0; i < 4; i++)
                    rb[i] = *(const float4*)(W_in + (size_t)(colBase + bcol[i]) * NIN + kc + bkq[i] * 4);
            }
            mm_k32(acc, sA + (ku & 1) * SA_BUF, sB + (ku & 1) * SB_BUF, r0, c0);
            if (ku + 1 < 32) STORE_AB((ku + 1) & 1);
            __syncthreads();
        }
#pragma unroll
        for (int rp = 0; rp < 4; rp++) {
            float2 p0 = unp(acc[rp][0]), p1 = unp(acc[rp][1]);
            float2 p2 = unp(acc[rp][2]), p3 = unp(acc[rp][3]);
            float4 lo = {p0.x, p1.x, p2.x, p3.x};
            float4 hi = {p0.y, p1.y, p2.y, p3.y};
            size_t rr = (size_t)rowBase + r0 + 2 * rp;
            *(float4*)(g_xp + rr * NH + colBase + c0) = lo;
            *(float4*)(g_xp + (rr + 1) * NH + colBase + c0) = hi;
        }
    }
    gbarf(epoch);

    // ---- time loop ----
    for (int t = 0; t < NT; t++) {
        for (int l = 0; l < 2; l++) {
            const float* hsrc = (l == 0) ? (g_h + NB * NM) : g_h;

            // ======== phase P: slab GEMM 8 coltiles x 16 K-splits ========
            {
                const int coltile = bid >> 4, split = bid & 15;
                const int kb = split * 32, colBase = coltile * 256;
                const float* Wb = (l == 0) ? fb_W : g_cWc;
                ull acc[4][4];
#pragma unroll
                for (int i = 0; i < 4; i++)
#pragma unroll
                    for (int j = 0; j < 4; j++) acc[i][j] = 0ull;
                float4 ra, rb[4];
                ra = *(const float4*)(hsrc + (size_t)arow * NM + kb + akq * 4);
#pragma unroll
                for (int i = 0; i < 4; i++)
                    rb[i] = *(const float4*)(Wb + (size_t)(colBase + bcol[i]) * NM + kb + bkq[i] * 4);
                STORE_AB(0);
                __syncthreads();
                mm_k32(acc, sA, sB, r0, c0);
#pragma unroll
                for (int rp = 0; rp < 4; rp++) {
                    float2 p0 = unp(acc[rp][0]), p1 = unp(acc[rp][1]);
                    float2 p2 = unp(acc[rp][2]), p3 = unp(acc[rp][3]);
                    float4 lo = {p0.x, p1.x, p2.x, p3.x};
                    float4 hi = {p0.y, p1.y, p2.y, p3.y};
                    int row = r0 + 2 * rp;
                    *(float4*)(g_pp + ((size_t)split * NB + row) * NH + colBase + c0) = lo;
                    *(float4*)(g_pp + ((size_t)split * NB + row + 1) * NH + colBase + c0) = hi;
                }
            }
            gbarf(epoch);

            // ======== phase R: reduce P splits + biases + linraw + stat partials ====
            {
                const int row = bid >> 1, half = bid & 1;
                const int c = half * 1024 + tid * 2;
                float2 acc2 = {0.f, 0.f};
#pragma unroll
                for (int s = 0; s < 16; s++) {
                    float2 v = *(const float2*)(g_pp + ((size_t)s * NB + row) * NH + c);
                    acc2.x += v.x; acc2.y += v.y;
                }
                float2 val;
                if (l == 0) {
                    float fbscale = (t == 0) ? 0.f : 0.1f;
                    float2 xv = *(const float2*)(g_xp + ((size_t)row * NT + t) * NH + c);
                    float2 bi = *(const float2*)(b_in + c);
                    float2 fbb = *(const float2*)(fb_b + c);
                    val.x = xv.x + bi.x + fbscale * (acc2.x + fbb.x);
                    val.y = xv.y + bi.y + fbscale * (acc2.y + fbb.y);
                } else {
                    float2 cb = *(const float2*)(g_cbc + c);
                    val.x = acc2.x + cb.x;
                    val.y = acc2.y + cb.y;
                }
                *(float2*)(g_linraw + (size_t)row * NH + c) = val;
                float s1 = val.x + val.y;
                float s2 = val.x * val.x + val.y * val.y;
#pragma unroll
                for (int off = 16; off > 0; off >>= 1) {
                    s1 += __shfl_xor_sync(0xffffffffu, s1, off);
                    s2 += __shfl_xor_sync(0xffffffffu, s2, off);
                }
                if ((tid & 31) == 0) { sW1[tid >> 5] = s1; sW2[tid >> 5] = s2; }
                __syncthreads();
                if (tid == 0) {
                    float t1 = 0.f, t2 = 0.f;
#pragma unroll
                    for (int w = 0; w < 16; w++) { t1 += sW1[w]; t2 += sW2[w]; }
                    g_ps1[bid] = t1;
                    g_ps2[bid] = t2;
                }
            }
            gbarf(epoch);

            // ======== phase G: stacked-gate GEMM, LN fused in A-load ========
            {
                if (tid < NB) {
                    float s1 = g_ps1[2 * tid] + g_ps1[2 * tid + 1];
                    float s2 = g_ps2[2 * tid] + g_ps2[2 * tid + 1];
                    float mu = s1 * (1.f / NH);
                    sMu[tid] = mu;
                    sRi[tid] = rsqrtf(s2 * (1.f / NH) - mu * mu + 1e-5f);
                }
                __syncthreads();
                int split, nk, kb, outCol, ldb;
                const float* Wb;
                if (bid < 96) {
                    int coltile = bid / 24; split = bid % 24;
                    nk = (split < 8) ? 4 : 3;
                    kb = ((split < 8) ? 4 * split : 32 + 3 * (split - 8)) * 32;
                    int colBase = coltile * 256;
                    if (colBase < 512) Wb = upd_W + ((size_t)l * NM + colBase) * NHM;
                    else               Wb = rst_W + ((size_t)l * NM + colBase - 512) * NHM;
                    ldb = NHM; outCol = colBase;
                } else {
                    int b2 = bid - 96;
                    int coltile = b2 >> 4; split = b2 & 15;
                    nk = 4; kb = split * 128;
                    int colBase = coltile * 256;
                    Wb = cell_W + ((size_t)l * NM + colBase) * NH;
                    ldb = NH; outCol = 1024 + colBase;
                }
                const float* hself = g_h + l * NB * NM;
                const float* lnwl = ln_w + l * NH;
                const float* lnbl = ln_b + l * NH;
                ull acc[4][4];
#pragma unroll
                for (int i = 0; i < 4; i++)
#pragma unroll
                    for (int j = 0; j < 4; j++) acc[i][j] = 0ull;
                float4 ra, rb[4];
#define G_LOAD(KU) do { \
    int kc = kb + (KU) * 32; \
    int kg = kc + akq * 4; \
    if (kg < NH) { \
        ra = *(const float4*)(g_linraw + (size_t)arow * NH + kg); \
        float4 w = *(const float4*)(lnwl + kg); \
        float4 b2v = *(const float4*)(lnbl + kg); \
        float mu = sMu[arow], ri = sRi[arow]; \
        ra.x = (ra.x - mu) * ri * w.x + b2v.x; \
        ra.y = (ra.y - mu) * ri * w.y + b2v.y; \
        ra.z = (ra.z - mu) * ri * w.z + b2v.z; \
        ra.w = (ra.w - mu) * ri * w.w + b2v.w; \
    } else { \
        ra = *(const float4*)(hself + (size_t)arow * NM + (kg - NH)); \
    } \
    _Pragma("unroll") \
    for (int i2 = 0; i2 < 4; i2++) \
        rb[i2] = *(const float4*)(Wb + (size_t)bcol[i2] * ldb + kc + bkq[i2] * 4); \
} while (0)
                G_LOAD(0);
                STORE_AB(0);
                __syncthreads();
                for (int ku = 0; ku < nk; ku++) {
                    if (ku + 1 < nk) G_LOAD(ku + 1);
                    mm_k32(acc, sA + (ku & 1) * SA_BUF, sB + (ku & 1) * SB_BUF, r0, c0);
                    if (ku + 1 < nk) STORE_AB((ku + 1) & 1);
                    __syncthreads();
                }
#pragma unroll
                for (int rp = 0; rp < 4; rp++) {
                    float2 p0 = unp(acc[rp][0]), p1 = unp(acc[rp][1]);
                    float2 p2 = unp(acc[rp][2]), p3 = unp(acc[rp][3]);
                    float4 lo = {p0.x, p1.x, p2.x, p3.x};
                    float4 hi = {p0.y, p1.y, p2.y, p3.y};
                    int row = r0 + 2 * rp;
                    *(float4*)(g_gp + ((size_t)split * NB + row) * NG + outCol + c0) = lo;
                    *(float4*)(g_gp + ((size_t)split * NB + row + 1) * NG + outCol + c0) = hi;
                }
            }
            gbarf(epoch);

            // ======== phase C: split reduce + gates + mem-LN + write ========
            if (bid < NB) {
                int b = bid, m = tid;
                float* hl = g_h + l * NB * NM;
                float su = 0.f, sr = 0.f, sc = 0.f;
#pragma unroll
                for (int s = 0; s < 24; s++) {
                    size_t base = ((size_t)s * NB + b) * NG;
                    su += g_gp[base + m];
                    sr += g_gp[base + 512 + m];
                }
#pragma unroll
                for (int s = 0; s < 16; s++)
                    sc += g_gp[((size_t)s * NB + b) * NG + 1024 + m];
                int lm = l * NM + m;
                float u = 1.f / (1.f + expf(-(su + upd_b[lm])));
                float r = 1.f / (1.f + expf(-(sr + rst_b[lm])));
                float cand = tanhf(sc + cell_b[lm]);
                float d = g_dcoef[lm] * u;
                float hp = hl[(size_t)b * NM + m];
                float hn = d * (hp * r) + (1.f - d) * cand;
                float s1 = hn, s2 = hn * hn;
#pragma unroll
                for (int off = 16; off > 0; off >>= 1) {
                    s1 += __shfl_xor_sync(0xffffffffu, s1, off);
                    s2 += __shfl_xor_sync(0xffffffffu, s2, off);
                }
                if ((tid & 31) == 0) { sW1[tid >> 5] = s1; sW2[tid >> 5] = s2; }
                __syncthreads();
                if (tid == 0) {
                    float t1 = 0.f, t2 = 0.f;
#pragma unroll
                    for (int w = 0; w < 16; w++) { t1 += sW1[w]; t2 += sW2[w]; }
                    float mu = t1 * (1.f / NM);
                    sMu[0] = mu;
                    sRi[0] = rsqrtf(t2 * (1.f / NM) - mu * mu + 1e-5f);
                }
                __syncthreads();
                float v = (hn - sMu[0]) * sRi[0] * mn_w[lm] + mn_b[lm];
                hl[(size_t)b * NM + m] = v;
                if (l == 1) out[((size_t)b * NT + t) * NM + m] = v;
            }
            gbarf(epoch);
        }
    }

    // ---- final hidden states hT appended after outs [B,T,M] ----
    for (int i = bid * NTHR + tid; i < 2 * NB * NM; i += NBLK * NTHR)
        out[(size_t)NB * NT * NM + i] = g_h[i];
}

extern "C" void kernel_launch(void* const* d_in, const int* in_sizes, int n_in,
                              void* d_out, int out_size)
{
    const float* x      = (const float*)d_in[0];
    const float* hidden = (const float*)d_in[1];
    const float* W_in   = (const float*)d_in[2];
    const float* b_in   = (const float*)d_in[3];
    const float* cell_W = (const float*)d_in[4];
    const float* cell_b = (const float*)d_in[5];
    const float* upd_W  = (const float*)d_in[6];
    const float* upd_b  = (const float*)d_in[7];
    const float* rst_W  = (const float*)d_in[8];
    const float* rst_b  = (const float*)d_in[9];
    const float* tau    = (const float*)d_in[10];
    const float* lc_W   = (const float*)d_in[11];
    const float* lc_b   = (const float*)d_in[12];
    const float* sk_W   = (const float*)d_in[13];
    const float* sk_b   = (const float*)d_in[14];
    const float* fb_W   = (const float*)d_in[15];
    const float* fb_b   = (const float*)d_in[16];
    const float* ln_w   = (const float*)d_in[17];
    const float* ln_b   = (const float*)d_in[18];
    const float* mn_w   = (const float*)d_in[19];
    const float* mn_b   = (const float*)d_in[20];
    float* out = (float*)d_out;

    cudaFuncSetAttribute(ltc_all, cudaFuncAttributeMaxDynamicSharedMemorySize, DYN_BYTES);
    ltc_all<<<NBLK, NTHR, DYN_BYTES>>>(x, hidden, W_in, b_in, cell_W, cell_b,
                                       upd_W, upd_b, rst_W, rst_b, tau,
                                       lc_W, lc_b, sk_W, sk_b, fb_W, fb_b,
                                       ln_w, ln_b, mn_w, mn_b, out);
}

// round 10
// speedup vs baseline: 1.4214x; 1.0173x over previous
#include <cuda_runtime.h>
#include <cstddef>

typedef unsigned long long ull;

#define NB 64
#define NT 256
#define NIN 1024
#define NH 2048
#define NM 512
#define NG 1536
#define NBLK 128
#define NTHR 512

#define SA_STRIDE 96
#define SB_STRIDE 288
#define SA_BUF 3072
#define SB_BUF 9216
#define DYN_BYTES 98304

// ---------------- device scratch ----------------
__device__ float g_xp[(size_t)NB * NT * NH];
__device__ float g_h[2 * NB * NM];
__device__ float g_pp[(size_t)4 * NB * NH];     // P partials (4 splits)
__device__ float g_gp[(size_t)20 * NB * NG];    // G partials (20 splits)
__device__ float g_Wg[2ull * 1024 * 2560];      // [l][u|r rows][2560], li-cols scaled by lnw
__device__ float g_Wc[2ull * 512 * 2048];       // [l][cell rows][2048], scaled by lnw
__device__ float g_cWc[(size_t)NH * NM];        // sk_W + lc_W
__device__ float g_cbc[NH];                     // sk_b + lc_b
__device__ float g_bias0[NH];                   // b_in + 0.1*fb_b
__device__ float g_cs[2 * NG];                  // col-sums of scaled W
__device__ float g_dv[2 * NG];                  // W.lnb + gate bias
__device__ float g_dcoef[2 * NM];
__device__ float g_mu[NB];
__device__ float g_ri[NB];
__device__ unsigned g_cnt;
__device__ unsigned g_sense;

// ---------------- f32x2 helpers ----------------
__device__ __forceinline__ void fma2(ull &d, ull a, ull b) {
    asm("fma.rn.f32x2 %0, %1, %2, %0;" : "+l"(d) : "l"(a), "l"(b));
}
__device__ __forceinline__ ull dup2(float x) {
    ull r; asm("mov.b64 %0, {%1, %1};" : "=l"(r) : "f"(x)); return r;
}
__device__ __forceinline__ float2 unp(ull v) {
    float2 r; asm("mov.b64 {%0, %1}, %2;" : "=f"(r.x), "=f"(r.y) : "l"(v)); return r;
}

// ---------------- atomic grid barrier (R6 proven) ----------------
__device__ __forceinline__ void gbar(unsigned &sense) {
    __syncthreads();
    if (threadIdx.x == 0) {
        sense ^= 1u;
        __threadfence();
        unsigned a = atomicAdd(&g_cnt, 1u);
        if (a == NBLK - 1u) {
            g_cnt = 0u;
            asm volatile("st.global.release.gpu.u32 [%0], %1;"
                         :: "l"(&g_sense), "r"(sense) : "memory");
        } else {
            unsigned s;
            do {
                asm volatile("ld.global.acquire.gpu.u32 %0, [%1];"
                             : "=r"(s) : "l"(&g_sense) : "memory");
            } while (s != sense);
        }
    }
    __syncthreads();
}

// ---------------- raw layer-input value (pre-LN), vectorized by 4 ----------------
__device__ __forceinline__ float4 li_load(int l, int t, int row, int kg,
                                          const float* __restrict__ b_in) {
    float4 s;
    if (l == 0) {
        float4 xv = *(const float4*)(g_xp + ((size_t)row * NT + t) * NH + kg);
        if (t > 0) {
            const float* pb = g_pp + (size_t)row * NH + kg;
            float4 p0 = *(const float4*)(pb);
            float4 p1 = *(const float4*)(pb + (size_t)NB * NH);
            float4 p2 = *(const float4*)(pb + 2 * (size_t)NB * NH);
            float4 p3 = *(const float4*)(pb + 3 * (size_t)NB * NH);
            float4 b0 = *(const float4*)(g_bias0 + kg);
            s.x = xv.x + b0.x + 0.1f * ((p0.x + p1.x) + (p2.x + p3.x));
            s.y = xv.y + b0.y + 0.1f * ((p0.y + p1.y) + (p2.y + p3.y));
            s.z = xv.z + b0.z + 0.1f * ((p0.z + p1.z) + (p2.z + p3.z));
            s.w = xv.w + b0.w + 0.1f * ((p0.w + p1.w) + (p2.w + p3.w));
        } else {
            float4 bi = *(const float4*)(b_in + kg);
            s.x = xv.x + bi.x; s.y = xv.y + bi.y;
            s.z = xv.z + bi.z; s.w = xv.w + bi.w;
        }
    } else {
        const float* pb = g_pp + (size_t)row * NH + kg;
        float4 p0 = *(const float4*)(pb);
        float4 p1 = *(const float4*)(pb + (size_t)NB * NH);
        float4 p2 = *(const float4*)(pb + 2 * (size_t)NB * NH);
        float4 p3 = *(const float4*)(pb + 3 * (size_t)NB * NH);
        float4 cb = *(const float4*)(g_cbc + kg);
        s.x = cb.x + (p0.x + p1.x) + (p2.x + p3.x);
        s.y = cb.y + (p0.y + p1.y) + (p2.y + p3.y);
        s.z = cb.z + (p0.z + p1.z) + (p2.z + p3.z);
        s.w = cb.w + (p0.w + p1.w) + (p2.w + p3.w);
    }
    return s;
}

// ---------------- 64x256 tile inner (R6 proven) ----------------
__device__ __forceinline__ void mm_k32(ull acc[4][4], const float* sAb, const float* sBb,
                                       int r0, int c0) {
#pragma unroll 8
    for (int k = 0; k < 32; k++) {
        int rot = k & 28;
        const float* ar = sAb + k * SA_STRIDE + rot + r0;
        ull a0 = *(const ull*)(ar);
        ull a1 = *(const ull*)(ar + 2);
        ull a2 = *(const ull*)(ar + 4);
        ull a3 = *(const ull*)(ar + 6);
        float4 bf = *(const float4*)(sBb + k * SB_STRIDE + rot + c0);
        ull b0 = dup2(bf.x), b1 = dup2(bf.y), b2 = dup2(bf.z), b3 = dup2(bf.w);
        fma2(acc[0][0], a0, b0); fma2(acc[0][1], a0, b1); fma2(acc[0][2], a0, b2); fma2(acc[0][3], a0, b3);
        fma2(acc[1][0], a1, b0); fma2(acc[1][1], a1, b1); fma2(acc[1][2], a1, b2); fma2(acc[1][3], a1, b3);
        fma2(acc[2][0], a2, b0); fma2(acc[2][1], a2, b1); fma2(acc[2][2], a2, b2); fma2(acc[2][3], a2, b3);
        fma2(acc[3][0], a3, b0); fma2(acc[3][1], a3, b1); fma2(acc[3][2], a3, b2); fma2(acc[3][3], a3, b3);
    }
}

#define STORE_AB(bsel) do { \
    float* dA = sA + (bsel) * SA_BUF + (akq * 4) * SA_STRIDE + akq * 4 + arow; \
    dA[0] = ra.x; dA[SA_STRIDE] = ra.y; dA[2 * SA_STRIDE] = ra.z; dA[3 * SA_STRIDE] = ra.w; \
    _Pragma("unroll") \
    for (int i2 = 0; i2 < 4; i2++) { \
        float* dB = sB + (bsel) * SB_BUF + (bkq[i2] * 4) * SB_STRIDE + bkq[i2] * 4 + bcol[i2]; \
        dB[0] = rb[i2].x; dB[SB_STRIDE] = rb[i2].y; \
        dB[2 * SB_STRIDE] = rb[i2].z; dB[3 * SB_STRIDE] = rb[i2].w; \
    } \
} while (0)

__global__ void __launch_bounds__(NTHR)
ltc_all(const float* __restrict__ x,      const float* __restrict__ hidden,
        const float* __restrict__ W_in,   const float* __restrict__ b_in,
        const float* __restrict__ cell_W, const float* __restrict__ cell_b,
        const float* __restrict__ upd_W,  const float* __restrict__ upd_b,
        const float* __restrict__ rst_W,  const float* __restrict__ rst_b,
        const float* __restrict__ tau,
        const float* __restrict__ lc_W,   const float* __restrict__ lc_b,
        const float* __restrict__ sk_W,   const float* __restrict__ sk_b,
        const float* __restrict__ fb_W,   const float* __restrict__ fb_b,
        const float* __restrict__ ln_w,   const float* __restrict__ ln_b,
        const float* __restrict__ mn_w,   const float* __restrict__ mn_b,
        float* __restrict__ out)
{
    extern __shared__ float dyn[];
    float* sA = dyn;
    float* sB = dyn + 2 * SA_BUF;
    __shared__ float sW1[16], sW2[16];
    __shared__ float sStat[2];

    const int tid = threadIdx.x;
    const int bid = blockIdx.x;
    unsigned sense = *(volatile unsigned*)&g_sense;

    const int arow = tid >> 3, akq = tid & 7;
    int bcol[4], bkq[4];
#pragma unroll
    for (int i = 0; i < 4; i++) { int id = tid + i * NTHR; bcol[i] = id >> 3; bkq[i] = id & 7; }
    const int r0 = (tid >> 6) * 8;
    const int c0 = (tid & 63) * 4;

    // ================= init / precompute =================
    for (int i = bid * NTHR + tid; i < 2 * NB * NM; i += NBLK * NTHR)
        g_h[i] = hidden[i];
    for (size_t i = (size_t)bid * NTHR + tid; i < (size_t)NH * NM; i += (size_t)NBLK * NTHR)
        g_cWc[i] = sk_W[i] + lc_W[i];
    for (int i = bid * NTHR + tid; i < NH; i += NBLK * NTHR) {
        g_cbc[i] = sk_b[i] + lc_b[i];
        g_bias0[i] = b_in[i] + 0.1f * fb_b[i];
    }
    for (int i = bid * NTHR + tid; i < 2 * NM; i += NBLK * NTHR) {
        float tv = tau[i];
        float sp = (tv > 20.f) ? tv : log1pf(expf(tv));
        float tc = fminf(fmaxf(sp, 0.1f), 10.f);
        g_dcoef[i] = expf(-1.f / tc);
    }
    // scaled gate weights: rows u(0..511) r(512..1023), cols<2048 scaled by lnw
    for (size_t i = (size_t)bid * NTHR + tid; i < 2ull * 1024 * 2560; i += (size_t)NBLK * NTHR) {
        size_t l = i / (1024ull * 2560);
        size_t rem = i - l * (1024ull * 2560);
        int j = (int)(rem / 2560), k = (int)(rem % 2560);
        float w = (j < 512) ? upd_W[(l * 512 + j) * 2560 + k]
                            : rst_W[(l * 512 + (j - 512)) * 2560 + k];
        float sc = (k < 2048) ? ln_w[l * 2048 + k] : 1.f;
        g_Wg[i] = w * sc;
    }
    for (size_t i = (size_t)bid * NTHR + tid; i < 2ull * 512 * 2048; i += (size_t)NBLK * NTHR) {
        size_t l = i / (512ull * 2048);
        size_t rem = i - l * (512ull * 2048);
        int k = (int)(rem % 2048);
        g_Wc[i] = cell_W[i] * ln_w[l * 2048 + k];
    }
    // per-gate-row colsum (cs) and lnb-dot + bias (dv)
    {
        int gid = bid * NTHR + tid;
        if (gid < 2 * NG) {
            int l = gid / NG, j = gid % NG;
            const float* rowp; float bias;
            if (j < 512)       { rowp = upd_W  + ((size_t)l * 512 + j) * 2560;          bias = upd_b[l * 512 + j]; }
            else if (j < 1024) { rowp = rst_W  + ((size_t)l * 512 + (j - 512)) * 2560;  bias = rst_b[l * 512 + j - 512]; }
            else               { rowp = cell_W + ((size_t)l * 512 + (j - 1024)) * 2048; bias = cell_b[l * 512 + j - 1024]; }
            float cs = 0.f, dv = 0.f;
            const float* lwp = ln_w + l * 2048;
            const float* lbp = ln_b + l * 2048;
#pragma unroll 4
            for (int h = 0; h < 2048; h += 4) {
                float4 w = *(const float4*)(rowp + h);
                float4 lw = *(const float4*)(lwp + h);
                float4 lb = *(const float4*)(lbp + h);
                cs += (w.x * lw.x + w.y * lw.y) + (w.z * lw.z + w.w * lw.w);
                dv += (w.x * lb.x + w.y * lb.y) + (w.z * lb.z + w.w * lb.w);
            }
            g_cs[gid] = cs;
            g_dv[gid] = dv + bias;
        }
    }

    // input projection: xp = x . W_in^T (2048 tasks of 64x256, dbuf pipeline)
    for (int p = 0; p < 16; p++) {
        int task = bid + p * NBLK;
        int rowBase = (task >> 3) * 64, colBase = (task & 7) * 256;
        ull acc[4][4];
#pragma unroll
        for (int i = 0; i < 4; i++)
#pragma unroll
            for (int j = 0; j < 4; j++) acc[i][j] = 0ull;
        float4 ra, rb[4];
        ra = *(const float4*)(x + (size_t)(rowBase + arow) * NIN + akq * 4);
#pragma unroll
        for (int i = 0; i < 4; i++)
            rb[i] = *(const float4*)(W_in + (size_t)(colBase + bcol[i]) * NIN + bkq[i] * 4);
        STORE_AB(0);
        __syncthreads();
        for (int ku = 0; ku < 32; ku++) {
            if (ku + 1 < 32) {
                int kc = (ku + 1) * 32;
                ra = *(const float4*)(x + (size_t)(rowBase + arow) * NIN + kc + akq * 4);
#pragma unroll
                for (int i = 0; i < 4; i++)
                    rb[i] = *(const float4*)(W_in + (size_t)(colBase + bcol[i]) * NIN + kc + bkq[i] * 4);
            }
            mm_k32(acc, sA + (ku & 1) * SA_BUF, sB + (ku & 1) * SB_BUF, r0, c0);
            if (ku + 1 < 32) STORE_AB((ku + 1) & 1);
            __syncthreads();
        }
#pragma unroll
        for (int rp = 0; rp < 4; rp++) {
            float2 p0 = unp(acc[rp][0]), p1 = unp(acc[rp][1]);
            float2 p2 = unp(acc[rp][2]), p3 = unp(acc[rp][3]);
            float4 lo = {p0.x, p1.x, p2.x, p3.x};
            float4 hi = {p0.y, p1.y, p2.y, p3.y};
            size_t rr = (size_t)rowBase + r0 + 2 * rp;
            *(float4*)(g_xp + rr * NH + colBase + c0) = lo;
            *(float4*)(g_xp + (rr + 1) * NH + colBase + c0) = hi;
        }
    }
    gbar(sense);

    // ================= time loop =================
    for (int t = 0; t < NT; t++) {
        for (int l = 0; l < 2; l++) {
            const float* hsrc = (l == 0) ? (g_h + NB * NM) : g_h;

            // ===== phase P: raw projection partials, 32 coltiles(64) x 4 splits(K=128) =====
            {
                const int ct = bid >> 2, sp = bid & 3;
                const int colBase = ct * 64, kb = sp * 128;
                const float* Wp = (l == 0) ? fb_W : g_cWc;
                float* As = dyn;            // [128][68]
                float* Bs = dyn + 8704;     // [128][66]
#pragma unroll
                for (int i = 0; i < 4; i++) {
                    int id = tid + i * NTHR;
                    int row = id >> 5, kq = id & 31;
                    float4 v = *(const float4*)(hsrc + (size_t)row * NM + kb + kq * 4);
                    float* dA = As + (kq * 4) * 68 + row;
                    dA[0] = v.x; dA[68] = v.y; dA[136] = v.z; dA[204] = v.w;
                    float4 w = *(const float4*)(Wp + (size_t)(colBase + row) * NM + kb + kq * 4);
                    float* dB = Bs + (kq * 4) * 66 + row;
                    dB[0] = w.x; dB[66] = w.y; dB[132] = w.z; dB[198] = w.w;
                }
                __syncthreads();
                const int pr0 = (tid >> 5) * 4;
                const int pc0 = (tid & 31) * 2;
                ull acc[2][2] = {{0ull, 0ull}, {0ull, 0ull}};
#pragma unroll 8
                for (int k = 0; k < 128; k++) {
                    ulonglong2 av = *(const ulonglong2*)(As + k * 68 + pr0);
                    float2 bf = *(const float2*)(Bs + k * 66 + pc0);
                    ull b0 = dup2(bf.x), b1 = dup2(bf.y);
                    fma2(acc[0][0], av.x, b0); fma2(acc[0][1], av.x, b1);
                    fma2(acc[1][0], av.y, b0); fma2(acc[1][1], av.y, b1);
                }
                int gcol = colBase + pc0;
#pragma unroll
                for (int i = 0; i < 2; i++) {
                    float2 v0 = unp(acc[i][0]), v1 = unp(acc[i][1]);
                    *(float2*)(g_pp + ((size_t)sp * NB + pr0 + 2 * i) * NH + gcol) = make_float2(v0.x, v1.x);
                    *(float2*)(g_pp + ((size_t)sp * NB + pr0 + 2 * i + 1) * NH + gcol) = make_float2(v0.y, v1.y);
                }
            }
            gbar(sense);

            // ===== phase G: stats-free gate GEMM (112 blocks) + LN stats (16 blocks) =====
            if (bid < 112) {
                int sp, kb, outCol, ldb;
                const float* Wb;
                bool isli;
                if (bid < 80) {
                    int ct = bid / 20; sp = bid % 20; kb = sp * 128;
                    Wb = g_Wg + ((size_t)l * 1024 + ct * 256) * 2560;
                    ldb = 2560; outCol = ct * 256;
                    isli = (sp < 16);
                } else {
                    int b2 = bid - 80;
                    int ct = b2 >> 4; sp = b2 & 15; kb = sp * 128;
                    Wb = g_Wc + ((size_t)l * 512 + ct * 256) * 2048;
                    ldb = 2048; outCol = 1024 + ct * 256;
                    isli = true;
                }
                const float* hself = g_h + l * NB * NM;
                ull acc[4][4];
#pragma unroll
                for (int i = 0; i < 4; i++)
#pragma unroll
                    for (int j = 0; j < 4; j++) acc[i][j] = 0ull;
                float4 ra, rb[4];
#define G_LOAD(KU) do { \
    int kc = kb + (KU) * 32; \
    int kg = kc + akq * 4; \
    if (isli) ra = li_load(l, t, arow, kg, b_in); \
    else      ra = *(const float4*)(hself + (size_t)arow * NM + (kg - 2048)); \
    _Pragma("unroll") \
    for (int i2 = 0; i2 < 4; i2++) \
        rb[i2] = *(const float4*)(Wb + (size_t)bcol[i2] * ldb + kc + bkq[i2] * 4); \
} while (0)
                G_LOAD(0);
                STORE_AB(0);
                __syncthreads();
#pragma unroll
                for (int ku = 0; ku < 4; ku++) {
                    if (ku + 1 < 4) G_LOAD(ku + 1);
                    mm_k32(acc, sA + (ku & 1) * SA_BUF, sB + (ku & 1) * SB_BUF, r0, c0);
                    if (ku + 1 < 4) STORE_AB((ku + 1) & 1);
                    __syncthreads();
                }
#pragma unroll
                for (int rp = 0; rp < 4; rp++) {
                    float2 p0 = unp(acc[rp][0]), p1 = unp(acc[rp][1]);
                    float2 p2 = unp(acc[rp][2]), p3 = unp(acc[rp][3]);
                    float4 lo = {p0.x, p1.x, p2.x, p3.x};
                    float4 hi = {p0.y, p1.y, p2.y, p3.y};
                    int row = r0 + 2 * rp;
                    *(float4*)(g_gp + ((size_t)sp * NB + row) * NG + outCol + c0) = lo;
                    *(float4*)(g_gp + ((size_t)sp * NB + row + 1) * NG + outCol + c0) = hi;
                }
            } else {
                // LN stats: 16 blocks x 4 rows; 128 threads per row
                int q = bid - 112;
                int rgrp = tid >> 7;
                int row = 4 * q + rgrp;
                int hbase = (tid & 127) * 16;
                float s1 = 0.f, s2 = 0.f;
#pragma unroll
                for (int e = 0; e < 4; e++) {
                    float4 v = li_load(l, t, row, hbase + e * 4, b_in);
                    s1 += (v.x + v.y) + (v.z + v.w);
                    s2 += (v.x * v.x + v.y * v.y) + (v.z * v.z + v.w * v.w);
                }
#pragma unroll
                for (int off = 16; off > 0; off >>= 1) {
                    s1 += __shfl_xor_sync(0xffffffffu, s1, off);
                    s2 += __shfl_xor_sync(0xffffffffu, s2, off);
                }
                if ((tid & 31) == 0) {
                    sW1[rgrp * 4 + ((tid >> 5) & 3)] = s1;
                    sW2[rgrp * 4 + ((tid >> 5) & 3)] = s2;
                }
                __syncthreads();
                if (tid < 4) {
                    float t1 = (sW1[tid * 4] + sW1[tid * 4 + 1]) + (sW1[tid * 4 + 2] + sW1[tid * 4 + 3]);
                    float t2 = (sW2[tid * 4] + sW2[tid * 4 + 1]) + (sW2[tid * 4 + 2] + sW2[tid * 4 + 3]);
                    float mu = t1 * (1.f / NH);
                    g_mu[4 * q + tid] = mu;
                    g_ri[4 * q + tid] = rsqrtf(t2 * (1.f / NH) - mu * mu + 1e-5f);
                }
            }
            gbar(sense);

            // ===== phase C: gate reduce + LN-correction + cell + mem-LN =====
            if (bid < NB) {
                int b = bid, m = tid;
                float* hl = g_h + l * NB * NM;
                float mu = g_mu[b], ri = g_ri[b];
                float su = 0.f, sr = 0.f, sc = 0.f, suh = 0.f, srh = 0.f;
#pragma unroll
                for (int s = 0; s < 16; s++) {
                    size_t base = ((size_t)s * NB + b) * NG;
                    su += g_gp[base + m];
                    sr += g_gp[base + 512 + m];
                    sc += g_gp[base + 1024 + m];
                }
#pragma unroll
                for (int s = 16; s < 20; s++) {
                    size_t base = ((size_t)s * NB + b) * NG;
                    suh += g_gp[base + m];
                    srh += g_gp[base + 512 + m];
                }
                int lm = l * NM + m;
                int cj = l * NG;
                float pu = ri * (su - mu * g_cs[cj + m])        + suh + g_dv[cj + m];
                float pr = ri * (sr - mu * g_cs[cj + 512 + m])  + srh + g_dv[cj + 512 + m];
                float pc = ri * (sc - mu * g_cs[cj + 1024 + m])       + g_dv[cj + 1024 + m];
                float u = 1.f / (1.f + expf(-pu));
                float r = 1.f / (1.f + expf(-pr));
                float cand = tanhf(pc);
                float d = g_dcoef[lm] * u;
                float hp = hl[(size_t)b * NM + m];
                float hn = d * (hp * r) + (1.f - d) * cand;
                float s1 = hn, s2 = hn * hn;
#pragma unroll
                for (int off = 16; off > 0; off >>= 1) {
                    s1 += __shfl_xor_sync(0xffffffffu, s1, off);
                    s2 += __shfl_xor_sync(0xffffffffu, s2, off);
                }
                if ((tid & 31) == 0) { sW1[tid >> 5] = s1; sW2[tid >> 5] = s2; }
                __syncthreads();
                if (tid == 0) {
                    float t1 = 0.f, t2 = 0.f;
#pragma unroll
                    for (int w = 0; w < 16; w++) { t1 += sW1[w]; t2 += sW2[w]; }
                    float mu2 = t1 * (1.f / NM);
                    sStat[0] = mu2;
                    sStat[1] = rsqrtf(t2 * (1.f / NM) - mu2 * mu2 + 1e-5f);
                }
                __syncthreads();
                float v = (hn - sStat[0]) * sStat[1] * mn_w[lm] + mn_b[lm];
                hl[(size_t)b * NM + m] = v;
                if (l == 1) out[((size_t)b * NT + t) * NM + m] = v;
            }
            gbar(sense);
        }
    }

    // ---- final hidden states hT appended after outs [B,T,M] ----
    for (int i = bid * NTHR + tid; i < 2 * NB * NM; i += NBLK * NTHR)
        out[(size_t)NB * NT * NM + i] = g_h[i];
}

extern "C" void kernel_launch(void* const* d_in, const int* in_sizes, int n_in,
                              void* d_out, int out_size)
{
    const float* x      = (const float*)d_in[0];
    const float* hidden = (const float*)d_in[1];
    const float* W_in   = (const float*)d_in[2];
    const float* b_in   = (const float*)d_in[3];
    const float* cell_W = (const float*)d_in[4];
    const float* cell_b = (const float*)d_in[5];
    const float* upd_W  = (const float*)d_in[6];
    const float* upd_b  = (const float*)d_in[7];
    const float* rst_W  = (const float*)d_in[8];
    const float* rst_b  = (const float*)d_in[9];
    const float* tau    = (const float*)d_in[10];
    const float* lc_W   = (const float*)d_in[11];
    const float* lc_b   = (const float*)d_in[12];
    const float* sk_W   = (const float*)d_in[13];
    const float* sk_b   = (const float*)d_in[14];
    const float* fb_W   = (const float*)d_in[15];
    const float* fb_b   = (const float*)d_in[16];
    const float* ln_w   = (const float*)d_in[17];
    const float* ln_b   = (const float*)d_in[18];
    const float* mn_w   = (const float*)d_in[19];
    const float* mn_b   = (const float*)d_in[20];
    float* out = (float*)d_out;

    cudaFuncSetAttribute(ltc_all, cudaFuncAttributeMaxDynamicSharedMemorySize, DYN_BYTES);
    ltc_all<<<NBLK, NTHR, DYN_BYTES>>>(x, hidden, W_in, b_in, cell_W, cell_b,
                                       upd_W, upd_b, rst_W, rst_b, tau,
                                       lc_W, lc_b, sk_W, sk_b, fb_W, fb_b,
                                       ln_w, ln_b, mn_w, mn_b, out);
}

// round 12
// speedup vs baseline: 1.4453x; 1.0168x over previous
#include <cuda_runtime.h>
#include <cstddef>

typedef unsigned long long ull;

#define NB 64
#define NT 256
#define NIN 1024
#define NH 2048
#define NM 512
#define NG 1536
#define NBLK 256          // total blocks
#define GBLK 128          // blocks per group
#define NTHR 256
#define GB 32             // batch rows per group

#define SA_STR 64
#define SB_STR 288
#define SA_BUF 2048       // 32 k x 64
#define SB_BUF 9216       // 32 k x 288
#define DYN_BYTES 90112   // (2*2048 + 2*9216) * 4

// P-phase layout (K=128 resident slab)
#define PA_STR 64
#define PB_STR 96
#define PB_OFF 8192       // floats

// ---------------- device scratch ----------------
__device__ float g_xp[(size_t)NB * NT * NH];
__device__ float g_h[2 * NB * NM];
__device__ float g_pp[2ull * 4 * GB * NH];      // per-group P partials (4 splits)
__device__ float g_gp[2ull * 20 * GB * NG];     // per-group G partials (20 splits)
__device__ float g_Wg[2ull * 1024 * 2560];      // [l][u|r rows][2560], li-cols scaled by lnw
__device__ float g_Wc[2ull * 512 * 2048];       // [l][cell rows][2048], scaled by lnw
__device__ float g_cWc[(size_t)NH * NM];        // sk_W + lc_W
__device__ float g_cbc[NH];                     // sk_b + lc_b
__device__ float g_bias0[NH];                   // b_in + 0.1*fb_b
__device__ float g_cs[2 * NG];
__device__ float g_dv[2 * NG];
__device__ float g_dcoef[2 * NM];
__device__ float g_mu[2 * GB];
__device__ float g_ri[2 * GB];
__device__ unsigned g_gcnt, g_gsense;           // global barrier (zero-init)
__device__ unsigned g_cnt[64];                  // group barrier counters (idx g*32)
__device__ unsigned g_sns[64];                  // group barrier senses

// ---------------- f32x2 helpers ----------------
__device__ __forceinline__ void fma2(ull &d, ull a, ull b) {
    asm("fma.rn.f32x2 %0, %1, %2, %0;" : "+l"(d) : "l"(a), "l"(b));
}
__device__ __forceinline__ ull dup2(float x) {
    ull r; asm("mov.b64 %0, {%1, %1};" : "=l"(r) : "f"(x)); return r;
}
__device__ __forceinline__ float2 unp(ull v) {
    float2 r; asm("mov.b64 {%0, %1}, %2;" : "=f"(r.x), "=f"(r.y) : "l"(v)); return r;
}

// ---------------- barriers ----------------
__device__ __forceinline__ void bar_core(unsigned* cnt, unsigned* sns,
                                         unsigned total, unsigned &sense) {
    __syncthreads();
    if (threadIdx.x == 0) {
        sense ^= 1u;
        __threadfence();
        unsigned a = atomicAdd(cnt, 1u);
        if (a == total - 1u) {
            *cnt = 0u;
            asm volatile("st.global.release.gpu.u32 [%0], %1;"
                         :: "l"(sns), "r"(sense) : "memory");
        } else {
            unsigned s;
            do {
                asm volatile("ld.global.acquire.gpu.u32 %0, [%1];"
                             : "=r"(s) : "l"(sns) : "memory");
            } while (s != sense);
        }
    }
    __syncthreads();
}

// ---------------- raw layer-input value (pre-LN) ----------------
__device__ __forceinline__ float4 li_load(int l, int t, int row, int kg,
                                          const float* __restrict__ pp, int gb0,
                                          const float* __restrict__ b_in) {
    float4 s;
    if (l == 0) {
        float4 xv = *(const float4*)(g_xp + ((size_t)(gb0 + row) * NT + t) * NH + kg);
        if (t > 0) {
            const float* pb = pp + (size_t)row * NH + kg;
            float4 p0 = *(const float4*)(pb);
            float4 p1 = *(const float4*)(pb + (size_t)GB * NH);
            float4 p2 = *(const float4*)(pb + 2 * (size_t)GB * NH);
            float4 p3 = *(const float4*)(pb + 3 * (size_t)GB * NH);
            float4 b0 = *(const float4*)(g_bias0 + kg);
            s.x = xv.x + b0.x + 0.1f * ((p0.x + p1.x) + (p2.x + p3.x));
            s.y = xv.y + b0.y + 0.1f * ((p0.y + p1.y) + (p2.y + p3.y));
            s.z = xv.z + b0.z + 0.1f * ((p0.z + p1.z) + (p2.z + p3.z));
            s.w = xv.w + b0.w + 0.1f * ((p0.w + p1.w) + (p2.w + p3.w));
        } else {
            float4 bi = *(const float4*)(b_in + kg);
            s.x = xv.x + bi.x; s.y = xv.y + bi.y;
            s.z = xv.z + bi.z; s.w = xv.w + bi.w;
        }
    } else {
        const float* pb = pp + (size_t)row * NH + kg;
        float4 p0 = *(const float4*)(pb);
        float4 p1 = *(const float4*)(pb + (size_t)GB * NH);
        float4 p2 = *(const float4*)(pb + 2 * (size_t)GB * NH);
        float4 p3 = *(const float4*)(pb + 3 * (size_t)GB * NH);
        float4 cb = *(const float4*)(g_cbc + kg);
        s.x = cb.x + (p0.x + p1.x) + (p2.x + p3.x);
        s.y = cb.y + (p0.y + p1.y) + (p2.y + p3.y);
        s.z = cb.z + (p0.z + p1.z) + (p2.z + p3.z);
        s.w = cb.w + (p0.w + p1.w) + (p2.w + p3.w);
    }
    return s;
}

// ---------------- 32x256 tile inner: 32 k-steps, 8 rows x 4 cols per thread ----
__device__ __forceinline__ void mm_k32(ull acc[4][4], const float* sAb, const float* sBb,
                                       int r0, int c0) {
#pragma unroll 8
    for (int k = 0; k < 32; k++) {
        int rot = k & 28;
        const float* ar = sAb + k * SA_STR + rot + r0;
        ull a0 = *(const ull*)(ar);
        ull a1 = *(const ull*)(ar + 2);
        ull a2 = *(const ull*)(ar + 4);
        ull a3 = *(const ull*)(ar + 6);
        float4 bf = *(const float4*)(sBb + k * SB_STR + rot + c0);
        ull b0 = dup2(bf.x), b1 = dup2(bf.y), b2 = dup2(bf.z), b3 = dup2(bf.w);
        fma2(acc[0][0], a0, b0); fma2(acc[0][1], a0, b1); fma2(acc[0][2], a0, b2); fma2(acc[0][3], a0, b3);
        fma2(acc[1][0], a1, b0); fma2(acc[1][1], a1, b1); fma2(acc[1][2], a1, b2); fma2(acc[1][3], a1, b3);
        fma2(acc[2][0], a2, b0); fma2(acc[2][1], a2, b1); fma2(acc[2][2], a2, b2); fma2(acc[2][3], a2, b3);
        fma2(acc[3][0], a3, b0); fma2(acc[3][1], a3, b1); fma2(acc[3][2], a3, b2); fma2(acc[3][3], a3, b3);
    }
}

// A: 1 float4/thread (32 rows x 8 kq). B: 8 float4/thread (256 cols x 8 kq).
#define STORE_AB(bsel) do { \
    float* dA = sA + (bsel) * SA_BUF + (akq * 4) * SA_STR + akq * 4 + arow; \
    dA[0] = ra.x; dA[SA_STR] = ra.y; dA[2 * SA_STR] = ra.z; dA[3 * SA_STR] = ra.w; \
    _Pragma("unroll") \
    for (int i2 = 0; i2 < 8; i2++) { \
        float* dB = sB + (bsel) * SB_BUF + (bkq * 4) * SB_STR + bkq * 4 + bcol[i2]; \
        dB[0] = rb[i2].x; dB[SB_STR] = rb[i2].y; \
        dB[2 * SB_STR] = rb[i2].z; dB[3 * SB_STR] = rb[i2].w; \
    } \
} while (0)

__global__ void __launch_bounds__(NTHR, 2)
ltc_all(const float* __restrict__ x,      const float* __restrict__ hidden,
        const float* __restrict__ W_in,   const float* __restrict__ b_in,
        const float* __restrict__ cell_W, const float* __restrict__ cell_b,
        const float* __restrict__ upd_W,  const float* __restrict__ upd_b,
        const float* __restrict__ rst_W,  const float* __restrict__ rst_b,
        const float* __restrict__ tau,
        const float* __restrict__ lc_W,   const float* __restrict__ lc_b,
        const float* __restrict__ sk_W,   const float* __restrict__ sk_b,
        const float* __restrict__ fb_W,   const float* __restrict__ fb_b,
        const float* __restrict__ ln_w,   const float* __restrict__ ln_b,
        const float* __restrict__ mn_w,   const float* __restrict__ mn_b,
        float* __restrict__ out)
{
    extern __shared__ float dyn[];
    float* sA = dyn;
    float* sB = dyn + 2 * SA_BUF;
    __shared__ float sW1[8], sW2[8];
    __shared__ float sStat[2];

    const int tid = threadIdx.x;
    const int bid = blockIdx.x;
    const int group = bid >> 7;
    const int lbid = bid & (GBLK - 1);
    const int gb0 = group * GB;

    unsigned gsense, lsense;
    asm volatile("ld.global.acquire.gpu.u32 %0, [%1];" : "=r"(gsense) : "l"(&g_gsense) : "memory");
    asm volatile("ld.global.acquire.gpu.u32 %0, [%1];" : "=r"(lsense) : "l"(g_sns + group * 32) : "memory");

    float* pp = g_pp + (size_t)group * 4 * GB * NH;
    float* gp = g_gp + (size_t)group * 20 * GB * NG;

    const int arow = tid >> 3, akq = tid & 7;
    const int bkq = tid & 7;
    int bcol[8];
#pragma unroll
    for (int i = 0; i < 8; i++) bcol[i] = (tid >> 3) + i * 32;
    const int r0 = (tid >> 6) * 8;
    const int c0 = (tid & 63) * 4;

    // ================= global precompute (partitioned over 256 blocks) =========
    {
        size_t gt = (size_t)bid * NTHR + tid;
        const size_t GS = (size_t)NBLK * NTHR;
        for (size_t i = gt; i < 2 * NB * NM; i += GS) g_h[i] = hidden[i];
        for (size_t i = gt; i < (size_t)NH * NM; i += GS) g_cWc[i] = sk_W[i] + lc_W[i];
        for (size_t i = gt; i < NH; i += GS) {
            g_cbc[i] = sk_b[i] + lc_b[i];
            g_bias0[i] = b_in[i] + 0.1f * fb_b[i];
        }
        for (size_t i = gt; i < 2 * NM; i += GS) {
            float tv = tau[i];
            float sp = (tv > 20.f) ? tv : log1pf(expf(tv));
            float tc = fminf(fmaxf(sp, 0.1f), 10.f);
            g_dcoef[i] = expf(-1.f / tc);
        }
        for (size_t i = gt; i < 2ull * 1024 * 2560; i += GS) {
            size_t l = i / (1024ull * 2560);
            size_t rem = i - l * (1024ull * 2560);
            int j = (int)(rem / 2560), k = (int)(rem % 2560);
            float w = (j < 512) ? upd_W[(l * 512 + j) * 2560 + k]
                                : rst_W[(l * 512 + (j - 512)) * 2560 + k];
            float sc = (k < 2048) ? ln_w[l * 2048 + k] : 1.f;
            g_Wg[i] = w * sc;
        }
        for (size_t i = gt; i < 2ull * 512 * 2048; i += GS) {
            size_t l = i / (512ull * 2048);
            size_t rem = i - l * (512ull * 2048);
            int k = (int)(rem % 2048);
            g_Wc[i] = cell_W[i] * ln_w[l * 2048 + k];
        }
        if (gt < 2 * NG) {
            int l = (int)(gt / NG), j = (int)(gt % NG);
            const float* rowp; float bias;
            if (j < 512)       { rowp = upd_W  + ((size_t)l * 512 + j) * 2560;          bias = upd_b[l * 512 + j]; }
            else if (j < 1024) { rowp = rst_W  + ((size_t)l * 512 + (j - 512)) * 2560;  bias = rst_b[l * 512 + j - 512]; }
            else               { rowp = cell_W + ((size_t)l * 512 + (j - 1024)) * 2048; bias = cell_b[l * 512 + j - 1024]; }
            float cs = 0.f, dv = 0.f;
            const float* lwp = ln_w + l * 2048;
            const float* lbp = ln_b + l * 2048;
#pragma unroll 4
            for (int h = 0; h < 2048; h += 4) {
                float4 w = *(const float4*)(rowp + h);
                float4 lw = *(const float4*)(lwp + h);
                float4 lb = *(const float4*)(lbp + h);
                cs += (w.x * lw.x + w.y * lw.y) + (w.z * lw.z + w.w * lw.w);
                dv += (w.x * lb.x + w.y * lb.y) + (w.z * lb.z + w.w * lb.w);
            }
            g_cs[gt] = cs;
            g_dv[gt] = dv + bias;
        }
    }
    bar_core(&g_gcnt, &g_gsense, NBLK, gsense);

    // ===== input projection for this group's rows: 2048 tasks of 32x256 =====
    for (int p = 0; p < 16; p++) {
        int task = lbid + p * GBLK;
        int b_local = task >> 6, tt = (task >> 3) & 7, ct = task & 7;
        size_t rowBase = (size_t)(gb0 + b_local) * NT + tt * 32;
        int colBase = ct * 256;
        ull acc[4][4];
#pragma unroll
        for (int i = 0; i < 4; i++)
#pragma unroll
            for (int j = 0; j < 4; j++) acc[i][j] = 0ull;
        float4 ra, rb[8];
        ra = *(const float4*)(x + (rowBase + arow) * NIN + akq * 4);
#pragma unroll
        for (int i = 0; i < 8; i++)
            rb[i] = *(const float4*)(W_in + (size_t)(colBase + bcol[i]) * NIN + bkq * 4);
        STORE_AB(0);
        __syncthreads();
        for (int ku = 0; ku < 32; ku++) {
            if (ku + 1 < 32) {
                int kc = (ku + 1) * 32;
                ra = *(const float4*)(x + (rowBase + arow) * NIN + kc + akq * 4);
#pragma unroll
                for (int i = 0; i < 8; i++)
                    rb[i] = *(const float4*)(W_in + (size_t)(colBase + bcol[i]) * NIN + kc + bkq * 4);
            }
            mm_k32(acc, sA + (ku & 1) * SA_BUF, sB + (ku & 1) * SB_BUF, r0, c0);
            if (ku + 1 < 32) STORE_AB((ku + 1) & 1);
            __syncthreads();
        }
#pragma unroll
        for (int rp = 0; rp < 4; rp++) {
            float2 p0 = unp(acc[rp][0]), p1 = unp(acc[rp][1]);
            float2 p2 = unp(acc[rp][2]), p3 = unp(acc[rp][3]);
            float4 lo = {p0.x, p1.x, p2.x, p3.x};
            float4 hi = {p0.y, p1.y, p2.y, p3.y};
            size_t rr = rowBase + r0 + 2 * rp;
            *(float4*)(g_xp + rr * NH + colBase + c0) = lo;
            *(float4*)(g_xp + (rr + 1) * NH + colBase + c0) = hi;
        }
    }
    bar_core(g_cnt + group * 32, g_sns + group * 32, GBLK, lsense);

    // ================= time loop =================
    for (int t = 0; t < NT; t++) {
        for (int l = 0; l < 2; l++) {
            const float* hsrc = g_h + (((l == 0) ? 1 : 0) * NB + gb0) * NM;

            // ===== phase P: 32 coltiles(64) x 4 splits(K=128), tile 32x64x128 =====
            // FIXED layout: As stride 64 (fits row 31 + rot 28), Bs stride 96
            // (fits col 63 + rot 28); rotation (kq*4)&28 at store == k&28 at read.
            {
                const int ct = lbid >> 2, sp = lbid & 3;
                const int colBase = ct * 64, kb = sp * 128;
                const float* Wp = (l == 0) ? fb_W : g_cWc;
                float* As = dyn;             // [128][64]
                float* Bs = dyn + PB_OFF;    // [128][96]
#pragma unroll
                for (int i = 0; i < 4; i++) {
                    int id = tid + i * NTHR;
                    int row = id >> 5, kq = id & 31;
                    int rot = (kq * 4) & 28;
                    float4 v = *(const float4*)(hsrc + (size_t)row * NM + kb + kq * 4);
                    float* dA = As + (kq * 4) * PA_STR + rot + row;
                    dA[0] = v.x; dA[PA_STR] = v.y; dA[2 * PA_STR] = v.z; dA[3 * PA_STR] = v.w;
                }
#pragma unroll
                for (int i = 0; i < 8; i++) {
                    int id = tid + i * NTHR;
                    int col = id >> 5, kq = id & 31;
                    int rot = (kq * 4) & 28;
                    float4 w = *(const float4*)(Wp + (size_t)(colBase + col) * NM + kb + kq * 4);
                    float* dB = Bs + (kq * 4) * PB_STR + rot + col;
                    dB[0] = w.x; dB[PB_STR] = w.y; dB[2 * PB_STR] = w.z; dB[3 * PB_STR] = w.w;
                }
                __syncthreads();
                const int pr0 = (tid >> 5) * 4;
                const int pc0 = (tid & 31) * 2;
                ull acc[2][2] = {{0ull, 0ull}, {0ull, 0ull}};
#pragma unroll 8
                for (int k = 0; k < 128; k++) {
                    int rot = k & 28;
                    ulonglong2 av = *(const ulonglong2*)(As + k * PA_STR + rot + pr0);
                    float2 bf = *(const float2*)(Bs + k * PB_STR + rot + pc0);
                    ull b0 = dup2(bf.x), b1 = dup2(bf.y);
                    fma2(acc[0][0], av.x, b0); fma2(acc[0][1], av.x, b1);
                    fma2(acc[1][0], av.y, b0); fma2(acc[1][1], av.y, b1);
                }
                int gcol = colBase + pc0;
#pragma unroll
                for (int i = 0; i < 2; i++) {
                    float2 v0 = unp(acc[i][0]), v1 = unp(acc[i][1]);
                    *(float2*)(pp + ((size_t)sp * GB + pr0 + 2 * i) * NH + gcol) = make_float2(v0.x, v1.x);
                    *(float2*)(pp + ((size_t)sp * GB + pr0 + 2 * i + 1) * NH + gcol) = make_float2(v0.y, v1.y);
                }
            }
            bar_core(g_cnt + group * 32, g_sns + group * 32, GBLK, lsense);

            // ===== phase G: gate GEMM (112 blocks) + LN stats (16 blocks) =====
            if (lbid < 112) {
                int sp, kb, outCol, ldb;
                const float* Wb;
                bool isli;
                if (lbid < 80) {
                    int ct = lbid / 20; sp = lbid % 20; kb = sp * 128;
                    Wb = g_Wg + ((size_t)l * 1024 + ct * 256) * 2560;
                    ldb = 2560; outCol = ct * 256;
                    isli = (sp < 16);
                } else {
                    int b2 = lbid - 80;
                    int ct = b2 >> 4; sp = b2 & 15; kb = sp * 128;
                    Wb = g_Wc + ((size_t)l * 512 + ct * 256) * 2048;
                    ldb = 2048; outCol = 1024 + ct * 256;
                    isli = true;
                }
                const float* hself = g_h + (l * NB + gb0) * NM;
                ull acc[4][4];
#pragma unroll
                for (int i = 0; i < 4; i++)
#pragma unroll
                    for (int j = 0; j < 4; j++) acc[i][j] = 0ull;
                float4 ra, rb[8];
#define G_LOAD(KU) do { \
    int kc = kb + (KU) * 32; \
    int kg = kc + akq * 4; \
    if (isli) ra = li_load(l, t, arow, kg, pp, gb0, b_in); \
    else      ra = *(const float4*)(hself + (size_t)arow * NM + (kg - 2048)); \
    _Pragma("unroll") \
    for (int i2 = 0; i2 < 8; i2++) \
        rb[i2] = *(const float4*)(Wb + (size_t)bcol[i2] * ldb + kc + bkq * 4); \
} while (0)
                G_LOAD(0);
                STORE_AB(0);
                __syncthreads();
#pragma unroll
                for (int ku = 0; ku < 4; ku++) {
                    if (ku + 1 < 4) G_LOAD(ku + 1);
                    mm_k32(acc, sA + (ku & 1) * SA_BUF, sB + (ku & 1) * SB_BUF, r0, c0);
                    if (ku + 1 < 4) STORE_AB((ku + 1) & 1);
                    __syncthreads();
                }
#pragma unroll
                for (int rp = 0; rp < 4; rp++) {
                    float2 p0 = unp(acc[rp][0]), p1 = unp(acc[rp][1]);
                    float2 p2 = unp(acc[rp][2]), p3 = unp(acc[rp][3]);
                    float4 lo = {p0.x, p1.x, p2.x, p3.x};
                    float4 hi = {p0.y, p1.y, p2.y, p3.y};
                    int row = r0 + 2 * rp;
                    *(float4*)(gp + ((size_t)sp * GB + row) * NG + outCol + c0) = lo;
                    *(float4*)(gp + ((size_t)sp * GB + row + 1) * NG + outCol + c0) = hi;
                }
            } else {
                // LN stats: 16 blocks x 2 rows; 128 threads per row
                int q = lbid - 112;
                int rgrp = tid >> 7;
                int row = q * 2 + rgrp;
                int hbase = (tid & 127) * 16;
                float s1 = 0.f, s2 = 0.f;
#pragma unroll
                for (int e = 0; e < 4; e++) {
                    float4 v = li_load(l, t, row, hbase + e * 4, pp, gb0, b_in);
                    s1 += (v.x + v.y) + (v.z + v.w);
                    s2 += (v.x * v.x + v.y * v.y) + (v.z * v.z + v.w * v.w);
                }
#pragma unroll
                for (int off = 16; off > 0; off >>= 1) {
                    s1 += __shfl_xor_sync(0xffffffffu, s1, off);
                    s2 += __shfl_xor_sync(0xffffffffu, s2, off);
                }
                if ((tid & 31) == 0) {
                    sW1[rgrp * 4 + ((tid >> 5) & 3)] = s1;
                    sW2[rgrp * 4 + ((tid >> 5) & 3)] = s2;
                }
                __syncthreads();
                if (tid < 2) {
                    float t1 = (sW1[tid * 4] + sW1[tid * 4 + 1]) + (sW1[tid * 4 + 2] + sW1[tid * 4 + 3]);
                    float t2 = (sW2[tid * 4] + sW2[tid * 4 + 1]) + (sW2[tid * 4 + 2] + sW2[tid * 4 + 3]);
                    float mu = t1 * (1.f / NH);
                    g_mu[gb0 + q * 2 + tid] = mu;
                    g_ri[gb0 + q * 2 + tid] = rsqrtf(t2 * (1.f / NH) - mu * mu + 1e-5f);
                }
            }
            bar_core(g_cnt + group * 32, g_sns + group * 32, GBLK, lsense);

            // ===== phase C: gate reduce + LN-correction + cell + mem-LN =====
            if (lbid < GB) {
                int b_local = lbid;
                float* hl = g_h + (l * NB + gb0) * NM;
                float mu = g_mu[gb0 + b_local], ri = g_ri[gb0 + b_local];
                float hnv[2];
#pragma unroll
                for (int j = 0; j < 2; j++) {
                    int m = tid + j * NTHR;
                    float su = 0.f, sr = 0.f, sc = 0.f, suh = 0.f, srh = 0.f;
#pragma unroll
                    for (int s = 0; s < 16; s++) {
                        size_t base = ((size_t)s * GB + b_local) * NG;
                        su += gp[base + m];
                        sr += gp[base + 512 + m];
                        sc += gp[base + 1024 + m];
                    }
#pragma unroll
                    for (int s = 16; s < 20; s++) {
                        size_t base = ((size_t)s * GB + b_local) * NG;
                        suh += gp[base + m];
                        srh += gp[base + 512 + m];
                    }
                    int cj = l * NG;
                    float pu = ri * (su - mu * g_cs[cj + m])        + suh + g_dv[cj + m];
                    float pr = ri * (sr - mu * g_cs[cj + 512 + m])  + srh + g_dv[cj + 512 + m];
                    float pc = ri * (sc - mu * g_cs[cj + 1024 + m])       + g_dv[cj + 1024 + m];
                    float u = 1.f / (1.f + expf(-pu));
                    float r = 1.f / (1.f + expf(-pr));
                    float cand = tanhf(pc);
                    float d = g_dcoef[l * NM + m] * u;
                    float hp = hl[(size_t)b_local * NM + m];
                    hnv[j] = d * (hp * r) + (1.f - d) * cand;
                }
                float s1 = hnv[0] + hnv[1];
                float s2 = hnv[0] * hnv[0] + hnv[1] * hnv[1];
#pragma unroll
                for (int off = 16; off > 0; off >>= 1) {
                    s1 += __shfl_xor_sync(0xffffffffu, s1, off);
                    s2 += __shfl_xor_sync(0xffffffffu, s2, off);
                }
                if ((tid & 31) == 0) { sW1[tid >> 5] = s1; sW2[tid >> 5] = s2; }
                __syncthreads();
                if (tid == 0) {
                    float t1 = 0.f, t2 = 0.f;
#pragma unroll
                    for (int w = 0; w < 8; w++) { t1 += sW1[w]; t2 += sW2[w]; }
                    float mu2 = t1 * (1.f / NM);
                    sStat[0] = mu2;
                    sStat[1] = rsqrtf(t2 * (1.f / NM) - mu2 * mu2 + 1e-5f);
                }
                __syncthreads();
#pragma unroll
                for (int j = 0; j < 2; j++) {
                    int m = tid + j * NTHR;
                    int lm = l * NM + m;
                    float v = (hnv[j] - sStat[0]) * sStat[1] * mn_w[lm] + mn_b[lm];
                    hl[(size_t)b_local * NM + m] = v;
                    if (l == 1) out[((size_t)(gb0 + b_local) * NT + t) * NM + m] = v;
                }
            }
            bar_core(g_cnt + group * 32, g_sns + group * 32, GBLK, lsense);
        }
    }

    // ---- final hidden states hT (this group's rows, both layers) ----
#pragma unroll
    for (int l = 0; l < 2; l++) {
        size_t base = (size_t)(l * NB + gb0) * NM;
        for (int i = lbid * NTHR + tid; i < GB * NM; i += GBLK * NTHR)
            out[(size_t)NB * NT * NM + base + i] = g_h[base + i];
    }
}

extern "C" void kernel_launch(void* const* d_in, const int* in_sizes, int n_in,
                              void* d_out, int out_size)
{
    const float* x      = (const float*)d_in[0];
    const float* hidden = (const float*)d_in[1];
    const float* W_in   = (const float*)d_in[2];
    const float* b_in   = (const float*)d_in[3];
    const float* cell_W = (const float*)d_in[4];
    const float* cell_b = (const float*)d_in[5];
    const float* upd_W  = (const float*)d_in[6];
    const float* upd_b  = (const float*)d_in[7];
    const float* rst_W  = (const float*)d_in[8];
    const float* rst_b  = (const float*)d_in[9];
    const float* tau    = (const float*)d_in[10];
    const float* lc_W   = (const float*)d_in[11];
    const float* lc_b   = (const float*)d_in[12];
    const float* sk_W   = (const float*)d_in[13];
    const float* sk_b   = (const float*)d_in[14];
    const float* fb_W   = (const float*)d_in[15];
    const float* fb_b   = (const float*)d_in[16];
    const float* ln_w   = (const float*)d_in[17];
    const float* ln_b   = (const float*)d_in[18];
    const float* mn_w   = (const float*)d_in[19];
    const float* mn_b   = (const float*)d_in[20];
    float* out = (float*)d_out;

    cudaFuncSetAttribute(ltc_all, cudaFuncAttributeMaxDynamicSharedMemorySize, DYN_BYTES);
    ltc_all<<<NBLK, NTHR, DYN_BYTES>>>(x, hidden, W_in, b_in, cell_W, cell_b,
                                       upd_W, upd_b, rst_W, rst_b, tau,
                                       lc_W, lc_b, sk_W, sk_b, fb_W, fb_b,
                                       ln_w, ln_b, mn_w, mn_b, out);
}

// round 13
// speedup vs baseline: 1.8463x; 1.2775x over previous
#include <cuda_runtime.h>
#include <cstddef>

typedef unsigned long long ull;

#define NB 64
#define NT 256
#define NIN 1024
#define NH 2048
#define NM 512
#define NROW (NB * NT)
#define NBLK 128
#define NTHR 512

// proj tile (64x256) smem layout (R6 proven)
#define SA_STRIDE 96
#define SB_STRIDE 288
#define SA_BUF 3072
#define SB_BUF 9216
// G tile (64x128, K=128 resident)
#define GA_STR 96
#define GB_STR 160
#define GB_OFF 12288
#define DYN_BYTES 131072

// ---------------- device scratch ----------------
__device__ float g_xp[(size_t)NROW * NH];       // x . W_in^T (no bias)
__device__ float g_X0[(size_t)NROW * 1536];     // Ŵ0 . (xp + bias0)
__device__ float g_aP[(size_t)NROW * NM];       // (xp+bias0) . P̃0
__device__ float g_h[2 * NB * NM];
__device__ float g_gp[(size_t)4 * NB * 3072];   // G split partials
__device__ float g_Ws[2ull * 1536 * NH];        // Ŵ (lnw-scaled gate+cell weights)
__device__ float g_PT[2ull * NM * NH];          // P̃^T
__device__ float g_Wcomp[2ull * 3072 * NM];     // [M | Wh | Q] composite
__device__ float g_bias0[NH];                   // b_in + 0.1 fb_b
__device__ float g_cs[2 * 1536];
__device__ float g_dv[2 * 1536];
__device__ float g_cv1[1536];                   // Ŵ1 . cbc
__device__ float g_fbadj[1536];                 // Ŵ0 . (0.1 fb_b)
__device__ float g_p1[2 * NM];                  // colsum P̃
__device__ float g_aP1c[NM];                    // cbc . P̃1
__device__ float g_c12[2];                      // Σcbc, Σcbc²
__device__ float g_A1[NROW];
__device__ float g_A2[NROW];
__device__ float g_A1z[NB];
__device__ float g_A2z[NB];
__device__ float g_dcoef[2 * NM];
__device__ unsigned g_cnt, g_sense;

// ---------------- f32x2 helpers ----------------
__device__ __forceinline__ void fma2(ull &d, ull a, ull b) {
    asm("fma.rn.f32x2 %0, %1, %2, %0;" : "+l"(d) : "l"(a), "l"(b));
}
__device__ __forceinline__ ull dup2(float x) {
    ull r; asm("mov.b64 %0, {%1, %1};" : "=l"(r) : "f"(x)); return r;
}
__device__ __forceinline__ float2 unp(ull v) {
    float2 r; asm("mov.b64 {%0, %1}, %2;" : "=f"(r.x), "=f"(r.y) : "l"(v)); return r;
}

// ---------------- atomic grid barrier (R6 proven) ----------------
__device__ __forceinline__ void gbar(unsigned &sense) {
    __syncthreads();
    if (threadIdx.x == 0) {
        sense ^= 1u;
        __threadfence();
        unsigned a = atomicAdd(&g_cnt, 1u);
        if (a == NBLK - 1u) {
            g_cnt = 0u;
            asm volatile("st.global.release.gpu.u32 [%0], %1;"
                         :: "l"(&g_sense), "r"(sense) : "memory");
        } else {
            unsigned s;
            do {
                asm volatile("ld.global.acquire.gpu.u32 %0, [%1];"
                             : "=r"(s) : "l"(&g_sense) : "memory");
            } while (s != sense);
        }
    }
    __syncthreads();
}

// ---------------- 64x256 proj tile inner (R6 proven) ----------------
__device__ __forceinline__ void mm_k32(ull acc[4][4], const float* sAb, const float* sBb,
                                       int r0, int c0) {
#pragma unroll 8
    for (int k = 0; k < 32; k++) {
        int rot = k & 28;
        const float* ar = sAb + k * SA_STRIDE + rot + r0;
        ull a0 = *(const ull*)(ar);
        ull a1 = *(const ull*)(ar + 2);
        ull a2 = *(const ull*)(ar + 4);
        ull a3 = *(const ull*)(ar + 6);
        float4 bf = *(const float4*)(sBb + k * SB_STRIDE + rot + c0);
        ull b0 = dup2(bf.x), b1 = dup2(bf.y), b2 = dup2(bf.z), b3 = dup2(bf.w);
        fma2(acc[0][0], a0, b0); fma2(acc[0][1], a0, b1); fma2(acc[0][2], a0, b2); fma2(acc[0][3], a0, b3);
        fma2(acc[1][0], a1, b0); fma2(acc[1][1], a1, b1); fma2(acc[1][2], a1, b2); fma2(acc[1][3], a1, b3);
        fma2(acc[2][0], a2, b0); fma2(acc[2][1], a2, b1); fma2(acc[2][2], a2, b2); fma2(acc[2][3], a2, b3);
        fma2(acc[3][0], a3, b0); fma2(acc[3][1], a3, b1); fma2(acc[3][2], a3, b2); fma2(acc[3][3], a3, b3);
    }
}

#define STORE_AB(bsel) do { \
    float* dA = sA + (bsel) * SA_BUF + (akq * 4) * SA_STRIDE + akq * 4 + arow; \
    dA[0] = ra.x; dA[SA_STRIDE] = ra.y; dA[2 * SA_STRIDE] = ra.z; dA[3 * SA_STRIDE] = ra.w; \
    _Pragma("unroll") \
    for (int i2 = 0; i2 < 4; i2++) { \
        float* dB = sB + (bsel) * SB_BUF + (bkq[i2] * 4) * SB_STRIDE + bkq[i2] * 4 + bcol[i2]; \
        dB[0] = rb[i2].x; dB[SB_STRIDE] = rb[i2].y; \
        dB[2 * SB_STRIDE] = rb[i2].z; dB[3 * SB_STRIDE] = rb[i2].w; \
    } \
} while (0)

__global__ void __launch_bounds__(NTHR)
ltc_all(const float* __restrict__ x,      const float* __restrict__ hidden,
        const float* __restrict__ W_in,   const float* __restrict__ b_in,
        const float* __restrict__ cell_W, const float* __restrict__ cell_b,
        const float* __restrict__ upd_W,  const float* __restrict__ upd_b,
        const float* __restrict__ rst_W,  const float* __restrict__ rst_b,
        const float* __restrict__ tau,
        const float* __restrict__ lc_W,   const float* __restrict__ lc_b,
        const float* __restrict__ sk_W,   const float* __restrict__ sk_b,
        const float* __restrict__ fb_W,   const float* __restrict__ fb_b,
        const float* __restrict__ ln_w,   const float* __restrict__ ln_b,
        const float* __restrict__ mn_w,   const float* __restrict__ mn_b,
        float* __restrict__ out)
{
    extern __shared__ float dyn[];
    float* sA  = dyn;                 // proj layout
    float* sB  = dyn + 2 * SA_BUF;
    float* gAs = dyn;                 // G layout
    float* gBs = dyn + GB_OFF;
    __shared__ float sRed[48];
    __shared__ float sOut[8];

    const int tid = threadIdx.x;
    const int bid = blockIdx.x;
    unsigned sense = *(volatile unsigned*)&g_sense;

    const int arow = tid >> 3, akq = tid & 7;
    int bcol[4], bkq[4];
#pragma unroll
    for (int i = 0; i < 4; i++) { int id = tid + i * NTHR; bcol[i] = id >> 3; bkq[i] = id & 7; }
    const int r0 = (tid >> 6) * 8;
    const int c0 = (tid & 63) * 4;

    const size_t gt = (size_t)bid * NTHR + tid;
    const size_t GS = (size_t)NBLK * NTHR;

    // ================= stage A: element-wise precompute + xp GEMM =================
    for (size_t i = gt; i < 2 * NB * NM; i += GS) g_h[i] = hidden[i];
    for (size_t i = gt; i < NH; i += GS) g_bias0[i] = b_in[i] + 0.1f * fb_b[i];
    for (size_t i = gt; i < 2 * NM; i += GS) {
        float tv = tau[i];
        float sp = (tv > 20.f) ? tv : log1pf(expf(tv));
        float tc = fminf(fmaxf(sp, 0.1f), 10.f);
        g_dcoef[i] = expf(-1.f / tc);
    }
    for (size_t i = gt; i < 2ull * 1536 * NH; i += GS) {
        size_t l = i / (1536ull * NH);
        size_t rem = i - l * 1536ull * NH;
        int j = (int)(rem / NH), h = (int)(rem % NH);
        float w = (j < 512)  ? upd_W[(l * 512 + j) * 2560 + h]
                : (j < 1024) ? rst_W[(l * 512 + (j - 512)) * 2560 + h]
                             : cell_W[(l * 512 + (j - 1024)) * (size_t)NH + h];
        g_Ws[i] = w * ln_w[l * NH + h];
    }
    for (size_t i = gt; i < 2ull * NH * NM; i += GS) {
        size_t l = i / ((size_t)NH * NM);
        size_t rem = i - l * (size_t)NH * NM;
        int h = (int)(rem / NM), m = (int)(rem % NM);
        float v = (l == 0) ? 0.1f * fb_W[(size_t)h * NM + m]
                           : sk_W[(size_t)h * NM + m] + lc_W[(size_t)h * NM + m];
        g_PT[l * (size_t)NM * NH + (size_t)m * NH + h] = v;
    }
    for (size_t i = gt; i < 2ull * 1024 * NM; i += GS) {
        size_t l = i / (1024ull * NM);
        size_t rem = i - l * 1024ull * NM;
        int jj = (int)(rem / NM), m = (int)(rem % NM);
        float w = (jj < 512) ? upd_W[(l * 512 + jj) * 2560 + 2048 + m]
                             : rst_W[(l * 512 + (jj - 512)) * 2560 + 2048 + m];
        g_Wcomp[l * 3072ull * NM + (size_t)(1536 + jj) * NM + m] = w;
    }
    if (gt < 2 * NM) {
        int l = (int)(gt / NM), m = (int)(gt % NM);
        float s = 0.f;
        for (int h = 0; h < NH; h++)
            s += (l == 0) ? 0.1f * fb_W[(size_t)h * NM + m]
                          : sk_W[(size_t)h * NM + m] + lc_W[(size_t)h * NM + m];
        g_p1[gt] = s;
    }
    if (gt < NM) {
        float s = 0.f;
        for (int h = 0; h < NH; h++)
            s += (sk_b[h] + lc_b[h]) * (sk_W[(size_t)h * NM + gt] + lc_W[(size_t)h * NM + gt]);
        g_aP1c[gt] = s;
    }
    if (gt == 0) {
        float s1 = 0.f, s2 = 0.f;
        for (int h = 0; h < NH; h++) { float c = sk_b[h] + lc_b[h]; s1 += c; s2 += c * c; }
        g_c12[0] = s1; g_c12[1] = s2;
    }
    if (gt < 4ull * 2 * 1536) {
        int q = (int)(gt & 3);
        int j4 = (int)(gt >> 2);
        int l = j4 / 1536, j = j4 % 1536;
        const float* rowp;
        float bias;
        if (j < 512)       { rowp = upd_W  + ((size_t)l * 512 + j) * 2560;          bias = upd_b[l * 512 + j]; }
        else if (j < 1024) { rowp = rst_W  + ((size_t)l * 512 + (j - 512)) * 2560;  bias = rst_b[l * 512 + j - 512]; }
        else               { rowp = cell_W + ((size_t)l * 512 + (j - 1024)) * (size_t)NH; bias = cell_b[l * 512 + j - 1024]; }
        float cs = 0.f, dvv = 0.f, aux = 0.f;
        for (int i = 0; i < 512; i++) {
            int h = q + 4 * i;
            float w = rowp[h];
            float lw = ln_w[l * NH + h], lb = ln_b[l * NH + h];
            cs += w * lw;
            dvv += w * lb;
            aux += (l == 0) ? w * lw * 0.1f * fb_b[h] : w * lw * (sk_b[h] + lc_b[h]);
        }
        cs  += __shfl_xor_sync(0xffffffffu, cs, 1);  cs  += __shfl_xor_sync(0xffffffffu, cs, 2);
        dvv += __shfl_xor_sync(0xffffffffu, dvv, 1); dvv += __shfl_xor_sync(0xffffffffu, dvv, 2);
        aux += __shfl_xor_sync(0xffffffffu, aux, 1); aux += __shfl_xor_sync(0xffffffffu, aux, 2);
        if (q == 0) {
            g_cs[j4] = cs;
            g_dv[j4] = dvv + bias;
            if (l == 0) g_fbadj[j] = aux; else g_cv1[j] = aux;
        }
    }

    // xp = x . W_in^T  (2048 tasks 64x256, K=1024)
    for (int p = 0; p < 16; p++) {
        int task = bid + p * NBLK;
        int rowBase = (task >> 3) * 64, colBase = (task & 7) * 256;
        ull acc[4][4];
#pragma unroll
        for (int i = 0; i < 4; i++)
#pragma unroll
            for (int j = 0; j < 4; j++) acc[i][j] = 0ull;
        float4 ra, rb[4];
        ra = *(const float4*)(x + (size_t)(rowBase + arow) * NIN + akq * 4);
#pragma unroll
        for (int i = 0; i < 4; i++)
            rb[i] = *(const float4*)(W_in + (size_t)(colBase + bcol[i]) * NIN + bkq[i] * 4);
        STORE_AB(0);
        __syncthreads();
        for (int ku = 0; ku < 32; ku++) {
            if (ku + 1 < 32) {
                int kc = (ku + 1) * 32;
                ra = *(const float4*)(x + (size_t)(rowBase + arow) * NIN + kc + akq * 4);
#pragma unroll
                for (int i = 0; i < 4; i++)
                    rb[i] = *(const float4*)(W_in + (size_t)(colBase + bcol[i]) * NIN + kc + bkq[i] * 4);
            }
            mm_k32(acc, sA + (ku & 1) * SA_BUF, sB + (ku & 1) * SB_BUF, r0, c0);
            if (ku + 1 < 32) STORE_AB((ku + 1) & 1);
            __syncthreads();
        }
#pragma unroll
        for (int rp = 0; rp < 4; rp++) {
            float2 p0 = unp(acc[rp][0]), p1 = unp(acc[rp][1]);
            float2 p2 = unp(acc[rp][2]), p3 = unp(acc[rp][3]);
            float4 lo = {p0.x, p1.x, p2.x, p3.x};
            float4 hi = {p0.y, p1.y, p2.y, p3.y};
            size_t rr = (size_t)rowBase + r0 + 2 * rp;
            *(float4*)(g_xp + rr * NH + colBase + c0) = lo;
            *(float4*)(g_xp + (rr + 1) * NH + colBase + c0) = hi;
        }
    }
    gbar(sense);

    // ================= stage B: derived GEMMs (2176 uniform 64x256xK2048 tasks) ====
    for (int p = 0; p < 17; p++) {
        int task = bid + p * NBLK;
        const float *Ap, *Bp;
        float* Cp;
        int ldc, rowBase, colBase, addb;
        if (task < 1536) {
            rowBase = (task / 6) * 64; colBase = (task % 6) * 256;
            Ap = g_xp; addb = 1; Bp = g_Ws; Cp = g_X0; ldc = 1536;
        } else if (task < 2048) {
            int tt = task - 1536;
            rowBase = (tt / 2) * 64; colBase = (tt % 2) * 256;
            Ap = g_xp; addb = 1; Bp = g_PT; Cp = g_aP; ldc = NM;
        } else if (task < 2080) {
            int tt = task - 2048; int l = tt / 16, q = tt % 16;
            rowBase = (q / 2) * 64; colBase = (q % 2) * 256;
            Ap = g_PT + (size_t)l * NM * NH; addb = 0;
            Bp = g_PT + (size_t)l * NM * NH;
            Cp = g_Wcomp + (size_t)l * 3072 * NM + 2560ull * NM; ldc = NM;
        } else {
            int tt = task - 2080; int l = tt / 48, q = tt % 48;
            rowBase = (q / 2) * 64; colBase = (q % 2) * 256;
            Ap = g_Ws + (size_t)l * 1536 * NH; addb = 0;
            Bp = g_PT + (size_t)l * NM * NH;
            Cp = g_Wcomp + (size_t)l * 3072 * NM; ldc = NM;
        }
        ull acc[4][4];
#pragma unroll
        for (int i = 0; i < 4; i++)
#pragma unroll
            for (int j = 0; j < 4; j++) acc[i][j] = 0ull;
        float4 ra, rb[4];
        {
            int kg = akq * 4;
            ra = *(const float4*)(Ap + (size_t)(rowBase + arow) * NH + kg);
            if (addb) {
                float4 bb = *(const float4*)(g_bias0 + kg);
                ra.x += bb.x; ra.y += bb.y; ra.z += bb.z; ra.w += bb.w;
            }
#pragma unroll
            for (int i = 0; i < 4; i++)
                rb[i] = *(const float4*)(Bp + (size_t)(colBase + bcol[i]) * NH + bkq[i] * 4);
        }
        STORE_AB(0);
        __syncthreads();
        for (int ku = 0; ku < 64; ku++) {
            if (ku + 1 < 64) {
                int kc = (ku + 1) * 32;
                int kg = kc + akq * 4;
                ra = *(const float4*)(Ap + (size_t)(rowBase + arow) * NH + kg);
                if (addb) {
                    float4 bb = *(const float4*)(g_bias0 + kg);
                    ra.x += bb.x; ra.y += bb.y; ra.z += bb.z; ra.w += bb.w;
                }
#pragma unroll
                for (int i = 0; i < 4; i++)
                    rb[i] = *(const float4*)(Bp + (size_t)(colBase + bcol[i]) * NH + kc + bkq[i] * 4);
            }
            mm_k32(acc, sA + (ku & 1) * SA_BUF, sB + (ku & 1) * SB_BUF, r0, c0);
            if (ku + 1 < 64) STORE_AB((ku + 1) & 1);
            __syncthreads();
        }
#pragma unroll
        for (int rp = 0; rp < 4; rp++) {
            float2 p0 = unp(acc[rp][0]), p1 = unp(acc[rp][1]);
            float2 p2 = unp(acc[rp][2]), p3 = unp(acc[rp][3]);
            float4 lo = {p0.x, p1.x, p2.x, p3.x};
            float4 hi = {p0.y, p1.y, p2.y, p3.y};
            size_t rr = (size_t)rowBase + r0 + 2 * rp;
            *(float4*)(Cp + rr * ldc + colBase + c0) = lo;
            *(float4*)(Cp + (rr + 1) * ldc + colBase + c0) = hi;
        }
    }
    // A1/A2 row stats (a = xp + bias0)
    {
        int q = tid & 3;
        int r = bid * 128 + (tid >> 2);
        float s1 = 0.f, s2 = 0.f;
        for (int i = 0; i < 512; i++) {
            int h = q + 4 * i;
            float a = g_xp[(size_t)r * NH + h] + g_bias0[h];
            s1 += a; s2 += a * a;
        }
        s1 += __shfl_xor_sync(0xffffffffu, s1, 1); s1 += __shfl_xor_sync(0xffffffffu, s1, 2);
        s2 += __shfl_xor_sync(0xffffffffu, s2, 1); s2 += __shfl_xor_sync(0xffffffffu, s2, 2);
        if (q == 0) { g_A1[r] = s1; g_A2[r] = s2; }
    }
    if (bid == 0 && tid < 256) {
        int q = tid & 3, b = tid >> 2;
        size_t base = (size_t)b * NT * NH;
        float s1 = 0.f, s2 = 0.f;
        for (int i = 0; i < 512; i++) {
            int h = q + 4 * i;
            float a = g_xp[base + h] + b_in[h];
            s1 += a; s2 += a * a;
        }
        s1 += __shfl_xor_sync(0xffffffffu, s1, 1); s1 += __shfl_xor_sync(0xffffffffu, s1, 2);
        s2 += __shfl_xor_sync(0xffffffffu, s2, 1); s2 += __shfl_xor_sync(0xffffffffu, s2, 2);
        if (q == 0) { g_A1z[b] = s1; g_A2z[b] = s2; }
    }
    gbar(sense);

    // ================= time loop =================
    for (int t = 0; t < NT; t++) {
        for (int l = 0; l < 2; l++) {
            const float* hoth = g_h + ((l == 0) ? NB * NM : 0);
            const float* hslf = g_h + ((l == 0) ? 0 : NB * NM);

            // ===== phase G: composite GEMM, 96 blocks x (64x128xK128) =====
            if (bid < 96) {
                int ct = bid >> 2, sp = bid & 3, kb = sp * 128;
                const float* Aop = (ct < 12 || ct >= 20) ? hoth : hslf;
                const float* Bop = g_Wcomp + (size_t)l * 3072 * NM + (size_t)(ct * 128) * NM;
                // loads
                float4 va[4], vb[8];
#pragma unroll
                for (int i = 0; i < 4; i++) {
                    int id = tid + i * NTHR;
                    va[i] = *(const float4*)(Aop + (size_t)(id >> 5) * NM + kb + (id & 31) * 4);
                }
#pragma unroll
                for (int i = 0; i < 8; i++) {
                    int id = tid + i * NTHR;
                    vb[i] = *(const float4*)(Bop + (size_t)(id >> 5) * NM + kb + (id & 31) * 4);
                }
#pragma unroll
                for (int i = 0; i < 4; i++) {
                    int id = tid + i * NTHR;
                    int row = id >> 5, kq = id & 31;
                    int rot = (kq * 4) & 28;
                    float* dA = gAs + (kq * 4) * GA_STR + rot + row;
                    dA[0] = va[i].x; dA[GA_STR] = va[i].y;
                    dA[2 * GA_STR] = va[i].z; dA[3 * GA_STR] = va[i].w;
                }
#pragma unroll
                for (int i = 0; i < 8; i++) {
                    int id = tid + i * NTHR;
                    int col = id >> 5, kq = id & 31;
                    int rot = (kq * 4) & 28;
                    float* dB = gBs + (kq * 4) * GB_STR + rot + col;
                    dB[0] = vb[i].x; dB[GB_STR] = vb[i].y;
                    dB[2 * GB_STR] = vb[i].z; dB[3 * GB_STR] = vb[i].w;
                }
                __syncthreads();
                const int gr0 = (tid >> 6) * 8;
                const int gc0 = (tid & 63) * 2;
                ull acc[4][2];
#pragma unroll
                for (int i = 0; i < 4; i++) { acc[i][0] = 0ull; acc[i][1] = 0ull; }
#pragma unroll 8
                for (int k = 0; k < 128; k++) {
                    int rot = k & 28;
                    const float* ar = gAs + k * GA_STR + rot + gr0;
                    ull a0 = *(const ull*)(ar);
                    ull a1 = *(const ull*)(ar + 2);
                    ull a2 = *(const ull*)(ar + 4);
                    ull a3 = *(const ull*)(ar + 6);
                    float2 bf = *(const float2*)(gBs + k * GB_STR + rot + gc0);
                    ull b0 = dup2(bf.x), b1 = dup2(bf.y);
                    fma2(acc[0][0], a0, b0); fma2(acc[0][1], a0, b1);
                    fma2(acc[1][0], a1, b0); fma2(acc[1][1], a1, b1);
                    fma2(acc[2][0], a2, b0); fma2(acc[2][1], a2, b1);
                    fma2(acc[3][0], a3, b0); fma2(acc[3][1], a3, b1);
                }
#pragma unroll
                for (int rp = 0; rp < 4; rp++) {
                    float2 v0 = unp(acc[rp][0]), v1 = unp(acc[rp][1]);
                    int row = gr0 + 2 * rp;
                    *(float2*)(g_gp + (size_t)(sp * NB + row) * 3072 + ct * 128 + gc0) =
                        make_float2(v0.x, v1.x);
                    *(float2*)(g_gp + (size_t)(sp * NB + row + 1) * 3072 + ct * 128 + gc0) =
                        make_float2(v0.y, v1.y);
                }
            }
            gbar(sense);

            // ===== phase C: stats assembly + gates + mem-LN =====
            if (bid < NB) {
                int b = bid, m = tid;
                float gs[6];
#pragma unroll
                for (int c = 0; c < 6; c++) {
                    float s = 0.f;
#pragma unroll
                    for (int sp = 0; sp < 4; sp++)
                        s += g_gp[(size_t)(sp * NB + b) * 3072 + c * 512 + m];
                    gs[c] = s;
                }
                float ho = hoth[b * NM + m];
                float hs = hslf[b * NM + m];
                float ph  = g_p1[l * NM + m] * ho;
                float aph = ((l == 0) ? g_aP[((size_t)b * NT + t) * NM + m] : g_aP1c[m]) * ho;
                float hqh = gs[5] * ho;
#pragma unroll
                for (int off = 16; off > 0; off >>= 1) {
                    ph  += __shfl_xor_sync(0xffffffffu, ph, off);
                    aph += __shfl_xor_sync(0xffffffffu, aph, off);
                    hqh += __shfl_xor_sync(0xffffffffu, hqh, off);
                }
                int w = tid >> 5;
                if ((tid & 31) == 0) { sRed[w] = ph; sRed[16 + w] = aph; sRed[32 + w] = hqh; }
                __syncthreads();
                if (tid == 0) {
                    float t0 = 0.f, t1 = 0.f, t2 = 0.f;
#pragma unroll
                    for (int i = 0; i < 16; i++) { t0 += sRed[i]; t1 += sRed[16 + i]; t2 += sRed[32 + i]; }
                    sOut[0] = t0; sOut[1] = t1; sOut[2] = t2;
                }
                __syncthreads();
                float S1, S2, fbf = 1.f;
                if (l == 0) {
                    if (t == 0) { S1 = g_A1z[b]; S2 = g_A2z[b]; fbf = 0.f; }
                    else {
                        S1 = g_A1[(size_t)b * NT + t] + sOut[0];
                        S2 = g_A2[(size_t)b * NT + t] + 2.f * sOut[1] + sOut[2];
                    }
                } else {
                    S1 = g_c12[0] + sOut[0];
                    S2 = g_c12[1] + 2.f * sOut[1] + sOut[2];
                }
                float mu = S1 * (1.f / NH);
                float ri = rsqrtf(S2 * (1.f / NH) - mu * mu + 1e-5f);
                float Xu, Xr, Xc;
                if (l == 0) {
                    const float* xb = g_X0 + ((size_t)b * NT + t) * 1536;
                    Xu = xb[m]; Xr = xb[512 + m]; Xc = xb[1024 + m];
                    if (t == 0) { Xu -= g_fbadj[m]; Xr -= g_fbadj[512 + m]; Xc -= g_fbadj[1024 + m]; }
                } else {
                    Xu = g_cv1[m]; Xr = g_cv1[512 + m]; Xc = g_cv1[1024 + m];
                }
                int cb = l * 1536;
                float pu = ri * (Xu + fbf * gs[0] - mu * g_cs[cb + m])        + g_dv[cb + m]        + gs[3];
                float pr = ri * (Xr + fbf * gs[1] - mu * g_cs[cb + 512 + m])  + g_dv[cb + 512 + m]  + gs[4];
                float pc = ri * (Xc + fbf * gs[2] - mu * g_cs[cb + 1024 + m]) + g_dv[cb + 1024 + m];
                float u = 1.f / (1.f + expf(-pu));
                float r = 1.f / (1.f + expf(-pr));
                float cand = tanhf(pc);
                float d = g_dcoef[l * NM + m] * u;
                float hn = d * (hs * r) + (1.f - d) * cand;
                float s1 = hn, s2 = hn * hn;
#pragma unroll
                for (int off = 16; off > 0; off >>= 1) {
                    s1 += __shfl_xor_sync(0xffffffffu, s1, off);
                    s2 += __shfl_xor_sync(0xffffffffu, s2, off);
                }
                if ((tid & 31) == 0) { sRed[w] = s1; sRed[16 + w] = s2; }
                __syncthreads();
                if (tid == 0) {
                    float t1 = 0.f, t2 = 0.f;
#pragma unroll
                    for (int i = 0; i < 16; i++) { t1 += sRed[i]; t2 += sRed[16 + i]; }
                    float mu2 = t1 * (1.f / NM);
                    sOut[3] = mu2;
                    sOut[4] = rsqrtf(t2 * (1.f / NM) - mu2 * mu2 + 1e-5f);
                }
                __syncthreads();
                float vv = (hn - sOut[3]) * sOut[4] * mn_w[l * NM + m] + mn_b[l * NM + m];
                g_h[(size_t)(l * NB + b) * NM + m] = vv;
                if (l == 1) out[((size_t)b * NT + t) * NM + m] = vv;
            }
            gbar(sense);
        }
    }

    // ---- final hidden states hT appended after outs [B,T,M] ----
    for (int i = bid * NTHR + tid; i < 2 * NB * NM; i += NBLK * NTHR)
        out[(size_t)NB * NT * NM + i] = g_h[i];
}

extern "C" void kernel_launch(void* const* d_in, const int* in_sizes, int n_in,
                              void* d_out, int out_size)
{
    const float* x      = (const float*)d_in[0];
    const float* hidden = (const float*)d_in[1];
    const float* W_in   = (const float*)d_in[2];
    const float* b_in   = (const float*)d_in[3];
    const float* cell_W = (const float*)d_in[4];
    const float* cell_b = (const float*)d_in[5];
    const float* upd_W  = (const float*)d_in[6];
    const float* upd_b  = (const float*)d_in[7];
    const float* rst_W  = (const float*)d_in[8];
    const float* rst_b  = (const float*)d_in[9];
    const float* tau    = (const float*)d_in[10];
    const float* lc_W   = (const float*)d_in[11];
    const float* lc_b   = (const float*)d_in[12];
    const float* sk_W   = (const float*)d_in[13];
    const float* sk_b   = (const float*)d_in[14];
    const float* fb_W   = (const float*)d_in[15];
    const float* fb_b   = (const float*)d_in[16];
    const float* ln_w   = (const float*)d_in[17];
    const float* ln_b   = (const float*)d_in[18];
    const float* mn_w   = (const float*)d_in[19];
    const float* mn_b   = (const float*)d_in[20];
    float* out = (float*)d_out;

    cudaFuncSetAttribute(ltc_all, cudaFuncAttributeMaxDynamicSharedMemorySize, DYN_BYTES);
    ltc_all<<<NBLK, NTHR, DYN_BYTES>>>(x, hidden, W_in, b_in, cell_W, cell_b,
                                       upd_W, upd_b, rst_W, rst_b, tau,
                                       lc_W, lc_b, sk_W, sk_b, fb_W, fb_b,
                                       ln_w, ln_b, mn_w, mn_b, out);
}